// round 13
// baseline (speedup 1.0000x reference)
#include <cuda_runtime.h>
#include <cuda_bf16.h>
#include <cuda_fp16.h>
#include <math.h>

#define MAXN 50000
#define MAXE 800000
#define SCAN_TILE 4096
#define MAX_BLKS ((MAXN + SCAN_TILE - 1) / SCAN_TILE + 1)

// ---------------- scratch (device globals; no allocation allowed) ----------------
__device__ int   g_is64;
__device__ __align__(16) int2  g_sd[MAXE];   // (src, dst) original order
__device__ int   g_rowptr[MAXN + 1];
__device__ int   g_cursor[MAXN];
__device__ int2  g_pair[MAXE];               // (src, ea-bits) sorted by dst
__device__ int   g_bsum[MAX_BLKS];
__device__ __align__(16) __half g_xl2h[(size_t)MAXN * 128];  // fp16 score operand
__device__ __align__(16) float  g_xr2[(size_t)MAXN * 128];
__device__ __align__(16) float2 g_pq[MAXN];  // (P, Q) per-node projection scalars
__device__ float g_p[MAXN];
__device__ float g_q[MAXN];
__device__ __align__(16) float4 g_cpack[64]; // att1-FOLDED: (cS,cD,cE,cC)*sa
__device__ float g_s41[64];                  // copysign(0.4, att1[j])
__device__ float g_aggA[64];
__device__ float g_aggC[64];
__device__ float g_u2[128];
__device__ float g_v2[128];
__device__ float g_wP[64];     // Wl2 @ Wd[:128]
__device__ float g_wQ[64];     // Wl2 @ Wd[128:]
__device__ float g_cP, g_cQ;   // bl2 @ Wd halves
__device__ float g_cB1, g_cB2; // bias2 @ Wd halves

// ---------------- precompute + int64 detect + cursor zero (fused) ----------------
__global__ void k_prez(const float* __restrict__ W_em, const float* __restrict__ b_em,
                       const float* __restrict__ W0,   const float* __restrict__ b0,
                       const float* __restrict__ Wl1,  const float* __restrict__ bl1,
                       const float* __restrict__ Wr1,  const float* __restrict__ br1,
                       const float* __restrict__ We1,  const float* __restrict__ We2,
                       const float* __restrict__ Wl2,  const float* __restrict__ bl2,
                       const float* __restrict__ bias2,const float* __restrict__ Wd,
                       const float* __restrict__ att1,
                       const void* __restrict__ ei, int N)
{
    int i = blockIdx.x * blockDim.x + threadIdx.x;
    if (i < N) g_cursor[i] = 0;
    if (blockIdx.x != 0) return;
    int t = threadIdx.x;
    if (t == 0) {
        const long long* p = (const long long*)ei;
        int is64 = 1;
        for (int k = 0; k < 8; k++) {
            long long v = p[k];
            if (v < 0 || v >= (1LL << 31)) { is64 = 0; break; }
        }
        g_is64 = is64;
    }
    // warp 7: the four 128-length dot products, parallel
    if (t >= 224 && t < 256) {
        int lane = t - 224;
        float cP = 0.f, cQ = 0.f, c1 = 0.f, c2 = 0.f;
        for (int j = lane; j < 128; j += 32) {
            float w1 = Wd[j], w2 = Wd[128 + j];
            cP = fmaf(bl2[j],   w1, cP);
            cQ = fmaf(bl2[j],   w2, cQ);
            c1 = fmaf(bias2[j], w1, c1);
            c2 = fmaf(bias2[j], w2, c2);
        }
        #pragma unroll
        for (int off = 16; off; off >>= 1) {
            cP += __shfl_xor_sync(0xffffffffu, cP, off);
            cQ += __shfl_xor_sync(0xffffffffu, cQ, off);
            c1 += __shfl_xor_sync(0xffffffffu, c1, off);
            c2 += __shfl_xor_sync(0xffffffffu, c2, off);
        }
        if (lane == 0) { g_cP = cP; g_cQ = cQ; g_cB1 = c1; g_cB2 = c2; }
    }
    if (t < 64) {
        float cS = 0.f, cD = 0.f, cE = 0.f;
        float Cl = bl1[t], Cr = br1[t], v1 = 0.f;
        for (int k = 0; k < 128; k++) {
            float wl = Wl1[k * 64 + t];
            float wr = Wr1[k * 64 + t];
            float we = We1[k * 64 + t];
            cS += W0[k]   * wl;
            cD += W0[k]   * wr;
            cE += W_em[k] * we;
            Cl += b0[k]   * wl;
            Cr += b0[k]   * wr;
            v1 += b_em[k] * we;
        }
        float sa = att1[t];
        float cC = Cl + Cr + v1;
        g_cpack[t] = make_float4(cS * sa, cD * sa, cE * sa, cC * sa);
        g_s41[t]  = copysignf(0.4f, sa);
        g_aggA[t] = cS;
        g_aggC[t] = Cl;
        // wP/wQ folds: Wl2[k, :] . Wd halves
        float wp = 0.f, wq = 0.f;
        for (int j = 0; j < 128; j++) {
            float w = Wl2[t * 128 + j];
            wp = fmaf(w, Wd[j], wp);
            wq = fmaf(w, Wd[128 + j], wq);
        }
        g_wP[t] = wp;
        g_wQ[t] = wq;
    }
    if (t >= 128 && t < 224) {
        // 96 threads handle 128 channels (t-128 and, for first 32, +96)
        for (int c = t - 128; c < 128; c += 96) {
            float u = 0.f, v = 0.f;
            for (int k = 0; k < 128; k++) {
                float w = We2[k * 128 + c];
                u = fmaf(W_em[k], w, u);
                v = fmaf(b_em[k], w, v);
            }
            g_u2[c] = u;
            g_v2[c] = v;
        }
    }
}

// ---------------- CSR build: 2 edges per thread ----------------
__global__ void k_convert(const void* __restrict__ ei, int E) {
    int t = blockIdx.x * blockDim.x + threadIdx.x;
    int e = 2 * t;
    if (e >= E) return;
    bool two = (e + 1 < E);
    int evenE = !(E & 1);
    int s0, d0, s1 = 0, d1 = 0;
    if (g_is64) {
        const long long* p = (const long long*)ei;
        longlong2 sv = ((const longlong2*)p)[t];
        s0 = (int)sv.x;
        if (two) s1 = (int)sv.y;
        if (evenE) {
            longlong2 dv = ((const longlong2*)(p + E))[t];
            d0 = (int)dv.x;
            if (two) d1 = (int)dv.y;
        } else {
            d0 = (int)p[E + e];
            if (two) d1 = (int)p[E + e + 1];
        }
    } else {
        const int* p = (const int*)ei;
        int2 sv = ((const int2*)p)[t];
        s0 = sv.x;
        if (two) s1 = sv.y;
        if (evenE) {
            int2 dv = ((const int2*)(p + E))[t];
            d0 = dv.x;
            if (two) d1 = dv.y;
        } else {
            d0 = p[E + e];
            if (two) d1 = p[E + e + 1];
        }
    }
    if (two) {
        ((int4*)g_sd)[t] = make_int4(s0, d0, s1, d1);
        atomicAdd(&g_cursor[d0], 1);
        atomicAdd(&g_cursor[d1], 1);
    } else {
        g_sd[e] = make_int2(s0, d0);
        atomicAdd(&g_cursor[d0], 1);
    }
}

// ---------------- parallel scan ----------------
__global__ void k_bsum(int n) {
    __shared__ int ws[32];
    int tid = threadIdx.x;                       // 1024
    int base = blockIdx.x * SCAN_TILE;
    int sum = 0;
    #pragma unroll
    for (int k = 0; k < 4; k++) {
        int i = base + tid + k * 1024;
        if (i < n) sum += g_cursor[i];
    }
    int lane = tid & 31, w = tid >> 5;
    #pragma unroll
    for (int off = 16; off; off >>= 1) sum += __shfl_xor_sync(0xffffffffu, sum, off);
    if (lane == 0) ws[w] = sum;
    __syncthreads();
    if (w == 0) {
        int v = ws[lane];
        #pragma unroll
        for (int off = 16; off; off >>= 1) v += __shfl_xor_sync(0xffffffffu, v, off);
        if (lane == 0) g_bsum[blockIdx.x] = v;
    }
}

__global__ void k_scan2(int n, int nb) {
    __shared__ int s[SCAN_TILE];
    __shared__ int ws[32];
    __shared__ int s_boff;
    int tid = threadIdx.x;                        // 1024
    int base = blockIdx.x * SCAN_TILE;
    if (tid < 32) {
        int v = (tid < nb && tid < blockIdx.x) ? g_bsum[tid] : 0;
        #pragma unroll
        for (int off = 16; off; off >>= 1) v += __shfl_xor_sync(0xffffffffu, v, off);
        if (tid == 0) s_boff = v;
    }
    #pragma unroll
    for (int k = 0; k < 4; k++) {
        int i = base + tid + k * 1024;
        s[tid + k * 1024] = (i < n) ? g_cursor[i] : 0;
    }
    __syncthreads();
    int a0 = s[4 * tid], a1 = s[4 * tid + 1], a2 = s[4 * tid + 2], a3 = s[4 * tid + 3];
    int tsum = a0 + a1 + a2 + a3;
    int lane = tid & 31, w = tid >> 5;
    int incl = tsum;
    #pragma unroll
    for (int off = 1; off < 32; off <<= 1) {
        int t = __shfl_up_sync(0xffffffffu, incl, off);
        if (lane >= off) incl += t;
    }
    if (lane == 31) ws[w] = incl;
    __syncthreads();
    if (w == 0) {
        int y = ws[lane];
        #pragma unroll
        for (int off = 1; off < 32; off <<= 1) {
            int t = __shfl_up_sync(0xffffffffu, y, off);
            if (lane >= off) y += t;
        }
        ws[lane] = y;
    }
    __syncthreads();
    int run = s_boff + incl - tsum + (w > 0 ? ws[w - 1] : 0);
    int pref[4] = {run, run + a0, run + a0 + a1, run + a0 + a1 + a2};
    int av[4] = {a0, a1, a2, a3};
    #pragma unroll
    for (int k = 0; k < 4; k++) {
        int i = base + 4 * tid + k;
        if (i < n) { g_rowptr[i] = pref[k]; g_cursor[i] = pref[k]; }
        if (i == n - 1) g_rowptr[n] = pref[k] + av[k];
    }
}

// ---------------- scatter: 4 edges per thread ----------------
__global__ void k_scatter(const float* __restrict__ ea, int E) {
    int t = blockIdx.x * blockDim.x + threadIdx.x;
    int e = 4 * t;
    if (e >= E) return;
    if (e + 4 <= E) {
        int4 sdA = ((const int4*)g_sd)[2 * t];
        int4 sdB = ((const int4*)g_sd)[2 * t + 1];
        float4 av = ((const float4*)ea)[t];
        int pos0 = atomicAdd(&g_cursor[sdA.y], 1);
        int pos1 = atomicAdd(&g_cursor[sdA.w], 1);
        int pos2 = atomicAdd(&g_cursor[sdB.y], 1);
        int pos3 = atomicAdd(&g_cursor[sdB.w], 1);
        g_pair[pos0] = make_int2(sdA.x, __float_as_int(av.x));
        g_pair[pos1] = make_int2(sdA.z, __float_as_int(av.y));
        g_pair[pos2] = make_int2(sdB.x, __float_as_int(av.z));
        g_pair[pos3] = make_int2(sdB.z, __float_as_int(av.w));
    } else {
        for (int j = e; j < E; j++) {
            int2 sd = g_sd[j];
            int pos = atomicAdd(&g_cursor[sd.y], 1);
            g_pair[pos] = make_int2(sd.x, __float_as_int(ea[j]));
        }
    }
}

// ---------------- fused layer1 + lin2 + PQ scalars (att1-folded |.|-form lrelu) ----------------
__global__ void k_layer12(const float* __restrict__ x,
                          const float* __restrict__ bias1,
                          const float* __restrict__ Wl, const float* __restrict__ bl,
                          const float* __restrict__ Wr, const float* __restrict__ br,
                          int N)
{
    __shared__ float4 sc[64];
    __shared__ float  s4[64];
    __shared__ float  sb1[64];
    __shared__ float  swP[64], swQ[64];
    __shared__ float  sH[64 * 64];       // h1 tile, 16 KB
    int tid = threadIdx.x;               // 256
    if (tid < 64) {
        sc[tid] = g_cpack[tid]; s4[tid] = g_s41[tid]; sb1[tid] = bias1[tid];
        swP[tid] = g_wP[tid]; swQ[tid] = g_wQ[tid];
    }
    __syncthreads();
    int warp = tid >> 5, lane = tid & 31;
    int tile0 = blockIdx.x * 64;

    // ---- phase 1: layer-1 attention, 8 nodes per warp ----
    for (int r = 0; r < 8; r++) {
        int n = tile0 + warp * 8 + r;
        int nl = warp * 8 + r;
        if (n >= N) break;
        int beg = g_rowptr[n], end = g_rowptr[n + 1];
        float xd = x[n];

        float mx[8], den[8], s1[8];
        #pragma unroll
        for (int h = 0; h < 8; h++) { mx[h] = -1e30f; den[h] = 0.f; s1[h] = 0.f; }

        int eix = beg + lane;
        for (; eix + 32 < end; eix += 64) {
            int2 p0 = g_pair[eix], p1 = g_pair[eix + 32];
            float xs0 = x[p0.x], xs1 = x[p1.x];
            float a0 = __int_as_float(p0.y), a1 = __int_as_float(p1.y);
            #pragma unroll
            for (int h = 0; h < 8; h++) {
                float v0 = 0.f, v1 = 0.f;
                #pragma unroll
                for (int c = 0; c < 8; c++) {
                    int j = h * 8 + c;
                    float4 q = sc[j];
                    float sg = s4[j];
                    float z0 = fmaf(q.x, xs0, fmaf(q.y, xd, fmaf(q.z, a0, q.w)));
                    float z1 = fmaf(q.x, xs1, fmaf(q.y, xd, fmaf(q.z, a1, q.w)));
                    v0 = fmaf(0.6f, z0, fmaf(sg, fabsf(z0), v0));
                    v1 = fmaf(0.6f, z1, fmaf(sg, fabsf(z1), v1));
                }
                float mb = fmaxf(v0, v1);
                float e0 = __expf(v0 - mb), e1 = __expf(v1 - mb);
                float mnew = fmaxf(mx[h], mb);
                float corr  = __expf(mx[h] - mnew);
                float scale = __expf(mb - mnew);
                den[h] = fmaf(den[h], corr, (e0 + e1) * scale);
                s1[h]  = fmaf(s1[h],  corr, fmaf(e0, xs0, e1 * xs1) * scale);
                mx[h] = mnew;
            }
        }
        if (eix < end) {
            int2 pr = g_pair[eix];
            float xs = x[pr.x];
            float a  = __int_as_float(pr.y);
            #pragma unroll
            for (int h = 0; h < 8; h++) {
                float scv = 0.f;
                #pragma unroll
                for (int c = 0; c < 8; c++) {
                    int j = h * 8 + c;
                    float4 q = sc[j];
                    float sg = s4[j];
                    float z = fmaf(q.x, xs, fmaf(q.y, xd, fmaf(q.z, a, q.w)));
                    scv = fmaf(0.6f, z, fmaf(sg, fabsf(z), scv));
                }
                float mnew = fmaxf(mx[h], scv);
                float corr = __expf(mx[h] - mnew);
                float ex   = __expf(scv - mnew);
                den[h] = fmaf(den[h], corr, ex);
                s1[h]  = fmaf(s1[h],  corr, ex * xs);
                mx[h] = mnew;
            }
        }
        #pragma unroll
        for (int h = 0; h < 8; h++) {
            float M = mx[h];
            #pragma unroll
            for (int off = 16; off; off >>= 1)
                M = fmaxf(M, __shfl_xor_sync(0xffffffffu, M, off));
            float corr = __expf(mx[h] - M);
            float d2 = den[h] * corr;
            float s2 = s1[h]  * corr;
            #pragma unroll
            for (int off = 16; off; off >>= 1) {
                d2 += __shfl_xor_sync(0xffffffffu, d2, off);
                s2 += __shfl_xor_sync(0xffffffffu, s2, off);
            }
            den[h] = d2; s1[h] = s2;
        }

        float s0 = (end > beg) ? 1.f : 0.f;
        float o0, o1;
        {
            int j = lane, h = j >> 3;
            float S1 = s1[h] / fmaxf(den[h], 1e-16f);
            o0 = fmaf(g_aggA[j], S1, fmaf(g_aggC[j], s0, sb1[j]));
            o0 = o0 > 0.f ? o0 : expm1f(o0);
            sH[nl * 64 + j] = o0;
        }
        {
            int j = lane + 32, h = j >> 3;
            float S1 = s1[h] / fmaxf(den[h], 1e-16f);
            o1 = fmaf(g_aggA[j], S1, fmaf(g_aggC[j], s0, sb1[j]));
            o1 = o1 > 0.f ? o1 : expm1f(o1);
            sH[nl * 64 + j] = o1;
        }
        // P/Q projection scalars: P = h1 . wP + cP
        float pv = fmaf(o0, swP[lane], o1 * swP[lane + 32]);
        float qv = fmaf(o0, swQ[lane], o1 * swQ[lane + 32]);
        #pragma unroll
        for (int off = 16; off; off >>= 1) {
            pv += __shfl_xor_sync(0xffffffffu, pv, off);
            qv += __shfl_xor_sync(0xffffffffu, qv, off);
        }
        if (lane == 0) g_pq[n] = make_float2(pv + g_cP, qv + g_cQ);
    }
    __syncthreads();

    // ---- phase 2: two GEMVs from smem h1; xl side stored as fp16 ----
    int half = tid >> 7;                   // 0 -> xl2h (fp16), 1 -> xr2 (fp32)
    int col  = tid & 127;
    const float* W = half ? Wr : Wl;
    const float* b = half ? br : bl;

    float wcol[64];
    float bb = b[col];
    #pragma unroll
    for (int k = 0; k < 64; k++) wcol[k] = W[k * 128 + col];

    int rows = min(64, N - tile0);
    for (int r = 0; r < rows; r++) {
        const float4* rv4 = (const float4*)&sH[r * 64];
        float acc = bb;
        #pragma unroll
        for (int k4 = 0; k4 < 16; k4++) {
            float4 rv = rv4[k4];
            acc = fmaf(rv.x, wcol[4 * k4 + 0], acc);
            acc = fmaf(rv.y, wcol[4 * k4 + 1], acc);
            acc = fmaf(rv.z, wcol[4 * k4 + 2], acc);
            acc = fmaf(rv.w, wcol[4 * k4 + 3], acc);
        }
        size_t idx = (size_t)(tile0 + r) * 128 + col;
        if (half) g_xr2[idx] = acc;
        else      g_xl2h[idx] = __float2half(acc);
    }
}

// ---------------- layer 2 attention: at-folded scores, fp16 gather, scalar P/Q ----------------
__global__ void k_attn2(const float* __restrict__ att2, int N)
{
    __shared__ float su[128], sv[128], sat[128];
    int tid = threadIdx.x;  // 256
    if (tid < 128) { su[tid] = g_u2[tid]; sv[tid] = g_v2[tid]; sat[tid] = att2[tid]; }
    __syncthreads();
    int warp = tid >> 5, lane = tid & 31;
    int n = blockIdx.x * 8 + warp;
    if (n >= N) return;
    int beg = g_rowptr[n], end = g_rowptr[n + 1];

    float4 xr = ((const float4*)(&g_xr2[(size_t)n * 128]))[lane];
    float xrv[4] = {xr.x, xr.y, xr.z, xr.w};
    float at[4], Up[4], XRV[4], s4[4];
    #pragma unroll
    for (int k = 0; k < 4; k++) {
        int ch = 4 * lane + k;
        float a = sat[ch];
        at[k]  = a;
        Up[k]  = su[ch] * a;
        XRV[k] = (xrv[k] + sv[ch]) * a;
        s4[k]  = copysignf(0.4f, a);
    }

    float mx = -1e30f, den = 0.f, accP = 0.f, accQ = 0.f;

    int ei = beg;
    for (; ei + 4 <= end; ei += 4) {
        float sc[4];
        float2 pq[4];
        #pragma unroll
        for (int j = 0; j < 4; j++) {
            int2 pr = g_pair[ei + j];
            uint2 hx = ((const uint2*)g_xl2h)[(size_t)pr.x * 32 + lane];
            pq[j] = g_pq[pr.x];
            float a = __int_as_float(pr.y);
            float2 lo = __half22float2(*(__half2*)&hx.x);
            float2 hi = __half22float2(*(__half2*)&hx.y);
            float xl[4] = {lo.x, lo.y, hi.x, hi.y};
            float t = 0.f;
            #pragma unroll
            for (int k = 0; k < 4; k++) {
                float wa = fmaf(xl[k], at[k], fmaf(a, Up[k], XRV[k]));
                t = fmaf(0.6f, wa, fmaf(s4[k], fabsf(wa), t));
            }
            sc[j] = t;
        }
        #pragma unroll
        for (int off = 16; off; off >>= 1) {
            #pragma unroll
            for (int j = 0; j < 4; j++)
                sc[j] += __shfl_xor_sync(0xffffffffu, sc[j], off);
        }
        float mb = fmaxf(fmaxf(sc[0], sc[1]), fmaxf(sc[2], sc[3]));
        float ex0 = __expf(sc[0] - mb), ex1 = __expf(sc[1] - mb);
        float ex2 = __expf(sc[2] - mb), ex3 = __expf(sc[3] - mb);
        float mnew = fmaxf(mx, mb);
        float corr  = __expf(mx - mnew);
        float scale = __expf(mb - mnew);
        den  = fmaf(den,  corr, (ex0 + ex1 + ex2 + ex3) * scale);
        float sp = fmaf(ex0, pq[0].x, fmaf(ex1, pq[1].x, fmaf(ex2, pq[2].x, ex3 * pq[3].x)));
        float sq = fmaf(ex0, pq[0].y, fmaf(ex1, pq[1].y, fmaf(ex2, pq[2].y, ex3 * pq[3].y)));
        accP = fmaf(accP, corr, sp * scale);
        accQ = fmaf(accQ, corr, sq * scale);
        mx = mnew;
    }
    for (; ei < end; ei++) {
        int2 pr = g_pair[ei];
        uint2 hx = ((const uint2*)g_xl2h)[(size_t)pr.x * 32 + lane];
        float2 pqv = g_pq[pr.x];
        float a = __int_as_float(pr.y);
        float2 lo = __half22float2(*(__half2*)&hx.x);
        float2 hi = __half22float2(*(__half2*)&hx.y);
        float xl[4] = {lo.x, lo.y, hi.x, hi.y};
        float sc = 0.f;
        #pragma unroll
        for (int k = 0; k < 4; k++) {
            float wa = fmaf(xl[k], at[k], fmaf(a, Up[k], XRV[k]));
            sc = fmaf(0.6f, wa, fmaf(s4[k], fabsf(wa), sc));
        }
        #pragma unroll
        for (int off = 16; off; off >>= 1) sc += __shfl_xor_sync(0xffffffffu, sc, off);
        float mnew = fmaxf(mx, sc);
        float corr = __expf(mx - mnew);
        float ex   = __expf(sc - mnew);
        den  = fmaf(den,  corr, ex);
        accP = fmaf(accP, corr, ex * pqv.x);
        accQ = fmaf(accQ, corr, ex * pqv.y);
        mx = mnew;
    }
    den = fmaxf(den, 1e-16f);
    if (lane == 0) {
        g_p[n] = accP / den + g_cB1;
        g_q[n] = accQ / den + g_cB2;
    }
}

// ---------------- final edge output: 2 edges per thread ----------------
__global__ void k_final(const float* __restrict__ bd, float* __restrict__ out, int E) {
    int t = blockIdx.x * blockDim.x + threadIdx.x;
    int e = 2 * t;
    if (e >= E) return;
    float b = bd[0];
    if (e + 1 < E) {
        int4 sd2 = ((const int4*)g_sd)[t];
        float2 o;
        o.x = g_p[sd2.x] + g_q[sd2.y] + b;
        o.y = g_p[sd2.z] + g_q[sd2.w] + b;
        ((float2*)out)[t] = o;
    } else {
        int2 sd = g_sd[e];
        out[e] = g_p[sd.x] + g_q[sd.y] + b;
    }
}

// ---------------- launch ----------------
extern "C" void kernel_launch(void* const* d_in, const int* in_sizes, int n_in,
                              void* d_out, int out_size)
{
    const float* x     = (const float*)d_in[0];
    const void*  ei    = d_in[1];
    const float* ea    = (const float*)d_in[2];
    const float* W_em  = (const float*)d_in[3];
    const float* b_em  = (const float*)d_in[4];
    const float* W0    = (const float*)d_in[5];
    const float* b0    = (const float*)d_in[6];
    const float* Wl1   = (const float*)d_in[7];
    const float* bl1   = (const float*)d_in[8];
    const float* Wr1   = (const float*)d_in[9];
    const float* br1   = (const float*)d_in[10];
    const float* We1   = (const float*)d_in[11];
    const float* att1  = (const float*)d_in[12];
    const float* bias1 = (const float*)d_in[13];
    const float* Wl2   = (const float*)d_in[14];
    const float* bl2   = (const float*)d_in[15];
    const float* Wr2   = (const float*)d_in[16];
    const float* br2   = (const float*)d_in[17];
    const float* We2   = (const float*)d_in[18];
    const float* att2  = (const float*)d_in[19];
    const float* bias2 = (const float*)d_in[20];
    const float* Wd    = (const float*)d_in[21];
    const float* bd    = (const float*)d_in[22];
    float* out = (float*)d_out;

    int N = in_sizes[0];
    int E = in_sizes[2];
    int NB = (N + SCAN_TILE - 1) / SCAN_TILE;
    int Eh = (E + 1) / 2;
    int Eq = (E + 3) / 4;

    k_prez<<<(N + 255) / 256, 256>>>(W_em, b_em, W0, b0, Wl1, bl1, Wr1, br1, We1, We2,
                                     Wl2, bl2, bias2, Wd, att1, ei, N);
    k_convert<<<(Eh + 255) / 256, 256>>>(ei, E);
    k_bsum<<<NB, 1024>>>(N);
    k_scan2<<<NB, 1024>>>(N, NB);
    k_scatter<<<(Eq + 255) / 256, 256>>>(ea, E);
    k_layer12<<<(N + 63) / 64, 256>>>(x, bias1, Wl2, bl2, Wr2, br2, N);
    k_attn2<<<(N + 7) / 8, 256>>>(att2, N);
    k_final<<<(Eh + 255) / 256, 256>>>(bd, out, E);
}

// round 15
// speedup vs baseline: 1.0702x; 1.0702x over previous
#include <cuda_runtime.h>
#include <cuda_bf16.h>
#include <cuda_fp16.h>
#include <math.h>

#define MAXN 50000
#define MAXE 800000
#define SCAN_TILE 4096
#define MAX_BLKS ((MAXN + SCAN_TILE - 1) / SCAN_TILE + 1)

// ---------------- scratch (device globals; no allocation allowed) ----------------
__device__ int   g_is64;
__device__ __align__(16) int2  g_sd[MAXE];   // (src, dst) original order
__device__ int   g_rowptr[MAXN + 1];
__device__ int   g_cursor[MAXN];
__device__ int2  g_pair[MAXE];               // (src, ea-bits) sorted by dst
__device__ int   g_bsum[MAX_BLKS];
__device__ __align__(16) __half g_xl2h[(size_t)MAXN * 128];  // fp16 score operand
__device__ __align__(16) float  g_xr2[(size_t)MAXN * 128];
__device__ __align__(16) float2 g_pq[MAXN];  // (P, Q) per-node projection scalars
__device__ float g_p[MAXN];
__device__ float g_q[MAXN];
__device__ __align__(16) float4 g_cpack[64]; // (cS, cD, cE, cC) per channel
__device__ float g_aggA[64];
__device__ float g_aggC[64];
__device__ float g_u2[128];
__device__ float g_v2[128];
__device__ float g_wP[64];     // Wl2 @ Wd[:128]
__device__ float g_wQ[64];     // Wl2 @ Wd[128:]
__device__ float g_cP, g_cQ;   // bl2 @ Wd halves
__device__ float g_cB1, g_cB2; // bias2 @ Wd halves

// ---------------- precompute + int64 detect + cursor zero (fused) ----------------
__global__ void k_prez(const float* __restrict__ W_em, const float* __restrict__ b_em,
                       const float* __restrict__ W0,   const float* __restrict__ b0,
                       const float* __restrict__ Wl1,  const float* __restrict__ bl1,
                       const float* __restrict__ Wr1,  const float* __restrict__ br1,
                       const float* __restrict__ We1,  const float* __restrict__ We2,
                       const float* __restrict__ Wl2,  const float* __restrict__ bl2,
                       const float* __restrict__ bias2,const float* __restrict__ Wd,
                       const void* __restrict__ ei, int N)
{
    int i = blockIdx.x * blockDim.x + threadIdx.x;
    if (i < N) g_cursor[i] = 0;
    if (blockIdx.x != 0) return;
    int t = threadIdx.x;
    if (t == 0) {
        const long long* p = (const long long*)ei;
        int is64 = 1;
        for (int k = 0; k < 8; k++) {
            long long v = p[k];
            if (v < 0 || v >= (1LL << 31)) { is64 = 0; break; }
        }
        g_is64 = is64;
    }
    // warp 7: the four 128-length dot products, parallel
    if (t >= 224 && t < 256) {
        int lane = t - 224;
        float cP = 0.f, cQ = 0.f, c1 = 0.f, c2 = 0.f;
        for (int j = lane; j < 128; j += 32) {
            float w1 = Wd[j], w2 = Wd[128 + j];
            cP = fmaf(bl2[j],   w1, cP);
            cQ = fmaf(bl2[j],   w2, cQ);
            c1 = fmaf(bias2[j], w1, c1);
            c2 = fmaf(bias2[j], w2, c2);
        }
        #pragma unroll
        for (int off = 16; off; off >>= 1) {
            cP += __shfl_xor_sync(0xffffffffu, cP, off);
            cQ += __shfl_xor_sync(0xffffffffu, cQ, off);
            c1 += __shfl_xor_sync(0xffffffffu, c1, off);
            c2 += __shfl_xor_sync(0xffffffffu, c2, off);
        }
        if (lane == 0) { g_cP = cP; g_cQ = cQ; g_cB1 = c1; g_cB2 = c2; }
    }
    if (t < 64) {
        float cS = 0.f, cD = 0.f, cE = 0.f;
        float Cl = bl1[t], Cr = br1[t], v1 = 0.f;
        for (int k = 0; k < 128; k++) {
            float wl = Wl1[k * 64 + t];
            float wr = Wr1[k * 64 + t];
            float we = We1[k * 64 + t];
            cS += W0[k]   * wl;
            cD += W0[k]   * wr;
            cE += W_em[k] * we;
            Cl += b0[k]   * wl;
            Cr += b0[k]   * wr;
            v1 += b_em[k] * we;
        }
        g_cpack[t] = make_float4(cS, cD, cE, Cl + Cr + v1);
        g_aggA[t] = cS;
        g_aggC[t] = Cl;
        float wp = 0.f, wq = 0.f;
        for (int j = 0; j < 128; j++) {
            float w = Wl2[t * 128 + j];
            wp = fmaf(w, Wd[j], wp);
            wq = fmaf(w, Wd[128 + j], wq);
        }
        g_wP[t] = wp;
        g_wQ[t] = wq;
    }
    if (t >= 128 && t < 224) {
        for (int c = t - 128; c < 128; c += 96) {
            float u = 0.f, v = 0.f;
            for (int k = 0; k < 128; k++) {
                float w = We2[k * 128 + c];
                u = fmaf(W_em[k], w, u);
                v = fmaf(b_em[k], w, v);
            }
            g_u2[c] = u;
            g_v2[c] = v;
        }
    }
}

// ---------------- CSR build: 2 edges per thread ----------------
__global__ void k_convert(const void* __restrict__ ei, int E) {
    int t = blockIdx.x * blockDim.x + threadIdx.x;
    int e = 2 * t;
    if (e >= E) return;
    bool two = (e + 1 < E);
    int evenE = !(E & 1);
    int s0, d0, s1 = 0, d1 = 0;
    if (g_is64) {
        const long long* p = (const long long*)ei;
        longlong2 sv = ((const longlong2*)p)[t];
        s0 = (int)sv.x;
        if (two) s1 = (int)sv.y;
        if (evenE) {
            longlong2 dv = ((const longlong2*)(p + E))[t];
            d0 = (int)dv.x;
            if (two) d1 = (int)dv.y;
        } else {
            d0 = (int)p[E + e];
            if (two) d1 = (int)p[E + e + 1];
        }
    } else {
        const int* p = (const int*)ei;
        int2 sv = ((const int2*)p)[t];
        s0 = sv.x;
        if (two) s1 = sv.y;
        if (evenE) {
            int2 dv = ((const int2*)(p + E))[t];
            d0 = dv.x;
            if (two) d1 = dv.y;
        } else {
            d0 = p[E + e];
            if (two) d1 = p[E + e + 1];
        }
    }
    if (two) {
        ((int4*)g_sd)[t] = make_int4(s0, d0, s1, d1);
        atomicAdd(&g_cursor[d0], 1);
        atomicAdd(&g_cursor[d1], 1);
    } else {
        g_sd[e] = make_int2(s0, d0);
        atomicAdd(&g_cursor[d0], 1);
    }
}

// ---------------- parallel scan ----------------
__global__ void k_bsum(int n) {
    __shared__ int ws[32];
    int tid = threadIdx.x;                       // 1024
    int base = blockIdx.x * SCAN_TILE;
    int sum = 0;
    #pragma unroll
    for (int k = 0; k < 4; k++) {
        int i = base + tid + k * 1024;
        if (i < n) sum += g_cursor[i];
    }
    int lane = tid & 31, w = tid >> 5;
    #pragma unroll
    for (int off = 16; off; off >>= 1) sum += __shfl_xor_sync(0xffffffffu, sum, off);
    if (lane == 0) ws[w] = sum;
    __syncthreads();
    if (w == 0) {
        int v = ws[lane];
        #pragma unroll
        for (int off = 16; off; off >>= 1) v += __shfl_xor_sync(0xffffffffu, v, off);
        if (lane == 0) g_bsum[blockIdx.x] = v;
    }
}

__global__ void k_scan2(int n, int nb) {
    __shared__ int s[SCAN_TILE];
    __shared__ int ws[32];
    __shared__ int s_boff;
    int tid = threadIdx.x;                        // 1024
    int base = blockIdx.x * SCAN_TILE;
    if (tid < 32) {
        int v = (tid < nb && tid < blockIdx.x) ? g_bsum[tid] : 0;
        #pragma unroll
        for (int off = 16; off; off >>= 1) v += __shfl_xor_sync(0xffffffffu, v, off);
        if (tid == 0) s_boff = v;
    }
    #pragma unroll
    for (int k = 0; k < 4; k++) {
        int i = base + tid + k * 1024;
        s[tid + k * 1024] = (i < n) ? g_cursor[i] : 0;
    }
    __syncthreads();
    int a0 = s[4 * tid], a1 = s[4 * tid + 1], a2 = s[4 * tid + 2], a3 = s[4 * tid + 3];
    int tsum = a0 + a1 + a2 + a3;
    int lane = tid & 31, w = tid >> 5;
    int incl = tsum;
    #pragma unroll
    for (int off = 1; off < 32; off <<= 1) {
        int t = __shfl_up_sync(0xffffffffu, incl, off);
        if (lane >= off) incl += t;
    }
    if (lane == 31) ws[w] = incl;
    __syncthreads();
    if (w == 0) {
        int y = ws[lane];
        #pragma unroll
        for (int off = 1; off < 32; off <<= 1) {
            int t = __shfl_up_sync(0xffffffffu, y, off);
            if (lane >= off) y += t;
        }
        ws[lane] = y;
    }
    __syncthreads();
    int run = s_boff + incl - tsum + (w > 0 ? ws[w - 1] : 0);
    int pref[4] = {run, run + a0, run + a0 + a1, run + a0 + a1 + a2};
    int av[4] = {a0, a1, a2, a3};
    #pragma unroll
    for (int k = 0; k < 4; k++) {
        int i = base + 4 * tid + k;
        if (i < n) { g_rowptr[i] = pref[k]; g_cursor[i] = pref[k]; }
        if (i == n - 1) g_rowptr[n] = pref[k] + av[k];
    }
}

// ---------------- scatter: 4 edges per thread ----------------
__global__ void k_scatter(const float* __restrict__ ea, int E) {
    int t = blockIdx.x * blockDim.x + threadIdx.x;
    int e = 4 * t;
    if (e >= E) return;
    if (e + 4 <= E) {
        int4 sdA = ((const int4*)g_sd)[2 * t];
        int4 sdB = ((const int4*)g_sd)[2 * t + 1];
        float4 av = ((const float4*)ea)[t];
        int pos0 = atomicAdd(&g_cursor[sdA.y], 1);
        int pos1 = atomicAdd(&g_cursor[sdA.w], 1);
        int pos2 = atomicAdd(&g_cursor[sdB.y], 1);
        int pos3 = atomicAdd(&g_cursor[sdB.w], 1);
        g_pair[pos0] = make_int2(sdA.x, __float_as_int(av.x));
        g_pair[pos1] = make_int2(sdA.z, __float_as_int(av.y));
        g_pair[pos2] = make_int2(sdB.x, __float_as_int(av.z));
        g_pair[pos3] = make_int2(sdB.z, __float_as_int(av.w));
    } else {
        for (int j = e; j < E; j++) {
            int2 sd = g_sd[j];
            int pos = atomicAdd(&g_cursor[sd.y], 1);
            g_pair[pos] = make_int2(sd.x, __float_as_int(ea[j]));
        }
    }
}

// ---------------- fused layer1 + lin2 + PQ scalars (R12 body) ----------------
__global__ void k_layer12(const float* __restrict__ x,
                          const float* __restrict__ att1, const float* __restrict__ bias1,
                          const float* __restrict__ Wl, const float* __restrict__ bl,
                          const float* __restrict__ Wr, const float* __restrict__ br,
                          int N)
{
    __shared__ float4 sc[64];
    __shared__ float  sa[64];
    __shared__ float  sb1[64];
    __shared__ float  swP[64], swQ[64];
    __shared__ float  sH[64 * 64];       // h1 tile, 16 KB
    int tid = threadIdx.x;               // 256
    if (tid < 64) {
        sc[tid] = g_cpack[tid]; sa[tid] = att1[tid]; sb1[tid] = bias1[tid];
        swP[tid] = g_wP[tid]; swQ[tid] = g_wQ[tid];
    }
    __syncthreads();
    int warp = tid >> 5, lane = tid & 31;
    int tile0 = blockIdx.x * 64;

    for (int r = 0; r < 8; r++) {
        int n = tile0 + warp * 8 + r;
        int nl = warp * 8 + r;
        if (n >= N) break;
        int beg = g_rowptr[n], end = g_rowptr[n + 1];
        float xd = x[n];

        float mx[8], den[8], s1[8];
        #pragma unroll
        for (int h = 0; h < 8; h++) { mx[h] = -1e30f; den[h] = 0.f; s1[h] = 0.f; }

        int eix = beg + lane;
        for (; eix + 32 < end; eix += 64) {
            int2 p0 = g_pair[eix], p1 = g_pair[eix + 32];
            float xs0 = x[p0.x], xs1 = x[p1.x];
            float a0 = __int_as_float(p0.y), a1 = __int_as_float(p1.y);
            #pragma unroll
            for (int h = 0; h < 8; h++) {
                float v0 = 0.f, v1 = 0.f;
                #pragma unroll
                for (int c = 0; c < 8; c++) {
                    int j = h * 8 + c;
                    float4 q = sc[j];
                    float m0 = fmaf(q.x, xs0, fmaf(q.y, xd, fmaf(q.z, a0, q.w)));
                    float m1 = fmaf(q.x, xs1, fmaf(q.y, xd, fmaf(q.z, a1, q.w)));
                    m0 = m0 > 0.f ? m0 : 0.2f * m0;
                    m1 = m1 > 0.f ? m1 : 0.2f * m1;
                    v0 = fmaf(m0, sa[j], v0);
                    v1 = fmaf(m1, sa[j], v1);
                }
                float mb = fmaxf(v0, v1);
                float e0 = __expf(v0 - mb), e1 = __expf(v1 - mb);
                float mnew = fmaxf(mx[h], mb);
                float corr  = __expf(mx[h] - mnew);
                float scale = __expf(mb - mnew);
                den[h] = fmaf(den[h], corr, (e0 + e1) * scale);
                s1[h]  = fmaf(s1[h],  corr, fmaf(e0, xs0, e1 * xs1) * scale);
                mx[h] = mnew;
            }
        }
        if (eix < end) {
            int2 pr = g_pair[eix];
            float xs = x[pr.x];
            float a  = __int_as_float(pr.y);
            #pragma unroll
            for (int h = 0; h < 8; h++) {
                float scv = 0.f;
                #pragma unroll
                for (int c = 0; c < 8; c++) {
                    int j = h * 8 + c;
                    float4 q = sc[j];
                    float m = fmaf(q.x, xs, fmaf(q.y, xd, fmaf(q.z, a, q.w)));
                    m = m > 0.f ? m : 0.2f * m;
                    scv = fmaf(m, sa[j], scv);
                }
                float mnew = fmaxf(mx[h], scv);
                float corr = __expf(mx[h] - mnew);
                float ex   = __expf(scv - mnew);
                den[h] = fmaf(den[h], corr, ex);
                s1[h]  = fmaf(s1[h],  corr, ex * xs);
                mx[h] = mnew;
            }
        }
        #pragma unroll
        for (int h = 0; h < 8; h++) {
            float M = mx[h];
            #pragma unroll
            for (int off = 16; off; off >>= 1)
                M = fmaxf(M, __shfl_xor_sync(0xffffffffu, M, off));
            float corr = __expf(mx[h] - M);
            float d2 = den[h] * corr;
            float s2 = s1[h]  * corr;
            #pragma unroll
            for (int off = 16; off; off >>= 1) {
                d2 += __shfl_xor_sync(0xffffffffu, d2, off);
                s2 += __shfl_xor_sync(0xffffffffu, s2, off);
            }
            den[h] = d2; s1[h] = s2;
        }

        float s0 = (end > beg) ? 1.f : 0.f;
        float o0, o1;
        {
            int j = lane, h = j >> 3;
            float S1 = s1[h] / fmaxf(den[h], 1e-16f);
            o0 = fmaf(g_aggA[j], S1, fmaf(g_aggC[j], s0, sb1[j]));
            o0 = o0 > 0.f ? o0 : expm1f(o0);
            sH[nl * 64 + j] = o0;
        }
        {
            int j = lane + 32, h = j >> 3;
            float S1 = s1[h] / fmaxf(den[h], 1e-16f);
            o1 = fmaf(g_aggA[j], S1, fmaf(g_aggC[j], s0, sb1[j]));
            o1 = o1 > 0.f ? o1 : expm1f(o1);
            sH[nl * 64 + j] = o1;
        }
        float pv = fmaf(o0, swP[lane], o1 * swP[lane + 32]);
        float qv = fmaf(o0, swQ[lane], o1 * swQ[lane + 32]);
        #pragma unroll
        for (int off = 16; off; off >>= 1) {
            pv += __shfl_xor_sync(0xffffffffu, pv, off);
            qv += __shfl_xor_sync(0xffffffffu, qv, off);
        }
        if (lane == 0) g_pq[n] = make_float2(pv + g_cP, qv + g_cQ);
    }
    __syncthreads();

    // ---- phase 2: two GEMVs from smem h1; xl side stored as fp16 ----
    int half = tid >> 7;                   // 0 -> xl2h (fp16), 1 -> xr2 (fp32)
    int col  = tid & 127;
    const float* W = half ? Wr : Wl;
    const float* b = half ? br : bl;

    float wcol[64];
    float bb = b[col];
    #pragma unroll
    for (int k = 0; k < 64; k++) wcol[k] = W[k * 128 + col];

    int rows = min(64, N - tile0);
    for (int r = 0; r < rows; r++) {
        const float4* rv4 = (const float4*)&sH[r * 64];
        float acc = bb;
        #pragma unroll
        for (int k4 = 0; k4 < 16; k4++) {
            float4 rv = rv4[k4];
            acc = fmaf(rv.x, wcol[4 * k4 + 0], acc);
            acc = fmaf(rv.y, wcol[4 * k4 + 1], acc);
            acc = fmaf(rv.z, wcol[4 * k4 + 2], acc);
            acc = fmaf(rv.w, wcol[4 * k4 + 3], acc);
        }
        size_t idx = (size_t)(tile0 + r) * 128 + col;
        if (half) g_xr2[idx] = acc;
        else      g_xl2h[idx] = __float2half(acc);
    }
}

// ---------------- layer 2 attention: 16-lane edge groups (group-scoped masks) ----------------
__global__ void k_attn2(const float* __restrict__ att2, int N)
{
    __shared__ float su[128], sv[128], sat[128];
    int tid = threadIdx.x;  // 256
    if (tid < 128) { su[tid] = g_u2[tid]; sv[tid] = g_v2[tid]; sat[tid] = att2[tid]; }
    __syncthreads();
    int warp = tid >> 5, lane = tid & 31;
    int grp = lane >> 4, sl = lane & 15;
    unsigned gmask = 0xFFFFu << (grp * 16);    // group-scoped shuffle mask
    int n = blockIdx.x * 8 + warp;
    if (n >= N) return;
    int beg = g_rowptr[n], end = g_rowptr[n + 1];
    int len = end - beg;
    int mid = beg + ((len + 1) >> 1);
    int gbeg = grp ? mid : beg;
    int gend = grp ? end : mid;

    // channels: ch = sl*8 + k. Per-lane constants (u, v+xr folded, at).
    float u[8], vv[8], at[8];
    {
        const float4* xr4 = (const float4*)(&g_xr2[(size_t)n * 128]);
        float4 xa = xr4[sl * 2], xb = xr4[sl * 2 + 1];
        float xrv[8] = {xa.x, xa.y, xa.z, xa.w, xb.x, xb.y, xb.z, xb.w};
        #pragma unroll
        for (int k = 0; k < 8; k++) {
            int ch = sl * 8 + k;
            u[k]  = su[ch];
            vv[k] = sv[ch] + xrv[k];
            at[k] = sat[ch];
        }
    }

    float mx = -1e30f, den = 0.f, accP = 0.f, accQ = 0.f;

    int i = gbeg;
    for (; i + 2 <= gend; i += 2) {
        int2 pr0 = g_pair[i], pr1 = g_pair[i + 1];
        uint4 h0 = ((const uint4*)g_xl2h)[(size_t)pr0.x * 16 + sl];
        uint4 h1 = ((const uint4*)g_xl2h)[(size_t)pr1.x * 16 + sl];
        float2 pq0 = g_pq[pr0.x], pq1 = g_pq[pr1.x];
        float a0 = __int_as_float(pr0.y), a1 = __int_as_float(pr1.y);
        float2 c00 = __half22float2(*(__half2*)&h0.x), c01 = __half22float2(*(__half2*)&h0.y);
        float2 c02 = __half22float2(*(__half2*)&h0.z), c03 = __half22float2(*(__half2*)&h0.w);
        float2 c10 = __half22float2(*(__half2*)&h1.x), c11 = __half22float2(*(__half2*)&h1.y);
        float2 c12 = __half22float2(*(__half2*)&h1.z), c13 = __half22float2(*(__half2*)&h1.w);
        float xl0[8] = {c00.x, c00.y, c01.x, c01.y, c02.x, c02.y, c03.x, c03.y};
        float xl1[8] = {c10.x, c10.y, c11.x, c11.y, c12.x, c12.y, c13.x, c13.y};
        float s0 = 0.f, s1 = 0.f;
        #pragma unroll
        for (int k = 0; k < 8; k++) {
            float m0 = xl0[k] + fmaf(a0, u[k], vv[k]);
            float m1 = xl1[k] + fmaf(a1, u[k], vv[k]);
            m0 = m0 > 0.f ? m0 : 0.2f * m0;
            m1 = m1 > 0.f ? m1 : 0.2f * m1;
            s0 = fmaf(m0, at[k], s0);
            s1 = fmaf(m1, at[k], s1);
        }
        #pragma unroll
        for (int off = 8; off; off >>= 1) {
            s0 += __shfl_xor_sync(gmask, s0, off, 16);
            s1 += __shfl_xor_sync(gmask, s1, off, 16);
        }
        float mb = fmaxf(s0, s1);
        float e0 = __expf(s0 - mb), e1 = __expf(s1 - mb);
        float mnew = fmaxf(mx, mb);
        float corr  = __expf(mx - mnew);
        float scale = __expf(mb - mnew);
        den  = fmaf(den,  corr, (e0 + e1) * scale);
        accP = fmaf(accP, corr, fmaf(e0, pq0.x, e1 * pq1.x) * scale);
        accQ = fmaf(accQ, corr, fmaf(e0, pq0.y, e1 * pq1.y) * scale);
        mx = mnew;
    }
    if (i < gend) {        // one remaining edge for this group
        int2 pr = g_pair[i];
        uint4 h0 = ((const uint4*)g_xl2h)[(size_t)pr.x * 16 + sl];
        float2 pqv = g_pq[pr.x];
        float a = __int_as_float(pr.y);
        float2 c0 = __half22float2(*(__half2*)&h0.x), c1 = __half22float2(*(__half2*)&h0.y);
        float2 c2 = __half22float2(*(__half2*)&h0.z), c3 = __half22float2(*(__half2*)&h0.w);
        float xl[8] = {c0.x, c0.y, c1.x, c1.y, c2.x, c2.y, c3.x, c3.y};
        float s0 = 0.f;
        #pragma unroll
        for (int k = 0; k < 8; k++) {
            float m = xl[k] + fmaf(a, u[k], vv[k]);
            m = m > 0.f ? m : 0.2f * m;
            s0 = fmaf(m, at[k], s0);
        }
        #pragma unroll
        for (int off = 8; off; off >>= 1)
            s0 += __shfl_xor_sync(gmask, s0, off, 16);
        float mnew = fmaxf(mx, s0);
        float corr = __expf(mx - mnew);
        float ex   = __expf(s0 - mnew);
        den  = fmaf(den,  corr, ex);
        accP = fmaf(accP, corr, ex * pqv.x);
        accQ = fmaf(accQ, corr, ex * pqv.y);
        mx = mnew;
    }
    // merge the two 16-lane groups (full warp reconverged here)
    __syncwarp();
    float Mo = __shfl_xor_sync(0xffffffffu, mx, 16);
    float M  = fmaxf(mx, Mo);
    float corr = __expf(mx - M);
    float d  = den  * corr;
    float pp = accP * corr;
    float qq = accQ * corr;
    d  += __shfl_xor_sync(0xffffffffu, d, 16);
    pp += __shfl_xor_sync(0xffffffffu, pp, 16);
    qq += __shfl_xor_sync(0xffffffffu, qq, 16);
    d = fmaxf(d, 1e-16f);
    if (lane == 0) {
        g_p[n] = pp / d + g_cB1;
        g_q[n] = qq / d + g_cB2;
    }
}

// ---------------- final edge output: 2 edges per thread ----------------
__global__ void k_final(const float* __restrict__ bd, float* __restrict__ out, int E) {
    int t = blockIdx.x * blockDim.x + threadIdx.x;
    int e = 2 * t;
    if (e >= E) return;
    float b = bd[0];
    if (e + 1 < E) {
        int4 sd2 = ((const int4*)g_sd)[t];
        float2 o;
        o.x = g_p[sd2.x] + g_q[sd2.y] + b;
        o.y = g_p[sd2.z] + g_q[sd2.w] + b;
        ((float2*)out)[t] = o;
    } else {
        int2 sd = g_sd[e];
        out[e] = g_p[sd.x] + g_q[sd.y] + b;
    }
}

// ---------------- launch ----------------
extern "C" void kernel_launch(void* const* d_in, const int* in_sizes, int n_in,
                              void* d_out, int out_size)
{
    const float* x     = (const float*)d_in[0];
    const void*  ei    = d_in[1];
    const float* ea    = (const float*)d_in[2];
    const float* W_em  = (const float*)d_in[3];
    const float* b_em  = (const float*)d_in[4];
    const float* W0    = (const float*)d_in[5];
    const float* b0    = (const float*)d_in[6];
    const float* Wl1   = (const float*)d_in[7];
    const float* bl1   = (const float*)d_in[8];
    const float* Wr1   = (const float*)d_in[9];
    const float* br1   = (const float*)d_in[10];
    const float* We1   = (const float*)d_in[11];
    const float* att1  = (const float*)d_in[12];
    const float* bias1 = (const float*)d_in[13];
    const float* Wl2   = (const float*)d_in[14];
    const float* bl2   = (const float*)d_in[15];
    const float* Wr2   = (const float*)d_in[16];
    const float* br2   = (const float*)d_in[17];
    const float* We2   = (const float*)d_in[18];
    const float* att2  = (const float*)d_in[19];
    const float* bias2 = (const float*)d_in[20];
    const float* Wd    = (const float*)d_in[21];
    const float* bd    = (const float*)d_in[22];
    float* out = (float*)d_out;

    int N = in_sizes[0];
    int E = in_sizes[2];
    int NB = (N + SCAN_TILE - 1) / SCAN_TILE;
    int Eh = (E + 1) / 2;
    int Eq = (E + 3) / 4;

    k_prez<<<(N + 255) / 256, 256>>>(W_em, b_em, W0, b0, Wl1, bl1, Wr1, br1, We1, We2,
                                     Wl2, bl2, bias2, Wd, ei, N);
    k_convert<<<(Eh + 255) / 256, 256>>>(ei, E);
    k_bsum<<<NB, 1024>>>(N);
    k_scan2<<<NB, 1024>>>(N, NB);
    k_scatter<<<(Eq + 255) / 256, 256>>>(ea, E);
    k_layer12<<<(N + 63) / 64, 256>>>(x, att1, bias1, Wl2, bl2, Wr2, br2, N);
    k_attn2<<<(N + 7) / 8, 256>>>(att2, N);
    k_final<<<(Eh + 255) / 256, 256>>>(bd, out, E);
}

// round 16
// speedup vs baseline: 1.4390x; 1.3446x over previous
#include <cuda_runtime.h>
#include <cuda_bf16.h>
#include <cuda_fp16.h>
#include <math.h>

#define MAXN 50000
#define MAXE 800000
#define SCAN_TILE 4096
#define MAX_BLKS ((MAXN + SCAN_TILE - 1) / SCAN_TILE + 1)

// ---------------- scratch (device globals; no allocation allowed) ----------------
__device__ int   g_is64;
__device__ __align__(16) int2  g_sd[MAXE];   // (src, dst) original order
__device__ int   g_rowptr[MAXN + 1];
__device__ int   g_cursor[MAXN];
__device__ int2  g_pair[MAXE];               // (src, ea-bits) sorted by dst
__device__ int   g_bsum[MAX_BLKS];
__device__ __align__(16) __half g_xl2h[(size_t)MAXN * 128];  // fp16 score operand
__device__ __align__(16) float  g_xr2[(size_t)MAXN * 128];
__device__ __align__(16) float2 g_pq[MAXN];  // (P, Q) per-node projection scalars
__device__ float g_p[MAXN];
__device__ float g_q[MAXN];
__device__ __align__(16) float4 g_cpack[64]; // (cS, cD, cE, cC) per channel
__device__ float g_aggA[64];
__device__ float g_aggC[64];
__device__ float g_u2[128];
__device__ float g_v2[128];
__device__ float g_wP[64];     // Wl2 @ Wd[:128]
__device__ float g_wQ[64];     // Wl2 @ Wd[128:]
__device__ float g_cP, g_cQ;   // bl2 @ Wd halves
__device__ float g_cB1, g_cB2; // bias2 @ Wd halves

// ---------------- precompute + int64 detect + cursor zero (fused) ----------------
__global__ void k_prez(const float* __restrict__ W_em, const float* __restrict__ b_em,
                       const float* __restrict__ W0,   const float* __restrict__ b0,
                       const float* __restrict__ Wl1,  const float* __restrict__ bl1,
                       const float* __restrict__ Wr1,  const float* __restrict__ br1,
                       const float* __restrict__ We1,  const float* __restrict__ We2,
                       const float* __restrict__ Wl2,  const float* __restrict__ bl2,
                       const float* __restrict__ bias2,const float* __restrict__ Wd,
                       const void* __restrict__ ei, int N)
{
    int i = blockIdx.x * blockDim.x + threadIdx.x;
    if (i < N) g_cursor[i] = 0;
    if (blockIdx.x != 0) return;
    int t = threadIdx.x;
    if (t == 0) {
        const long long* p = (const long long*)ei;
        int is64 = 1;
        for (int k = 0; k < 8; k++) {
            long long v = p[k];
            if (v < 0 || v >= (1LL << 31)) { is64 = 0; break; }
        }
        g_is64 = is64;
    }
    // warp 7: the four 128-length dot products, parallel
    if (t >= 224 && t < 256) {
        int lane = t - 224;
        float cP = 0.f, cQ = 0.f, c1 = 0.f, c2 = 0.f;
        for (int j = lane; j < 128; j += 32) {
            float w1 = Wd[j], w2 = Wd[128 + j];
            cP = fmaf(bl2[j],   w1, cP);
            cQ = fmaf(bl2[j],   w2, cQ);
            c1 = fmaf(bias2[j], w1, c1);
            c2 = fmaf(bias2[j], w2, c2);
        }
        #pragma unroll
        for (int off = 16; off; off >>= 1) {
            cP += __shfl_xor_sync(0xffffffffu, cP, off);
            cQ += __shfl_xor_sync(0xffffffffu, cQ, off);
            c1 += __shfl_xor_sync(0xffffffffu, c1, off);
            c2 += __shfl_xor_sync(0xffffffffu, c2, off);
        }
        if (lane == 0) { g_cP = cP; g_cQ = cQ; g_cB1 = c1; g_cB2 = c2; }
    }
    if (t < 64) {
        float cS = 0.f, cD = 0.f, cE = 0.f;
        float Cl = bl1[t], Cr = br1[t], v1 = 0.f;
        for (int k = 0; k < 128; k++) {
            float wl = Wl1[k * 64 + t];
            float wr = Wr1[k * 64 + t];
            float we = We1[k * 64 + t];
            cS += W0[k]   * wl;
            cD += W0[k]   * wr;
            cE += W_em[k] * we;
            Cl += b0[k]   * wl;
            Cr += b0[k]   * wr;
            v1 += b_em[k] * we;
        }
        g_cpack[t] = make_float4(cS, cD, cE, Cl + Cr + v1);
        g_aggA[t] = cS;
        g_aggC[t] = Cl;
        float wp = 0.f, wq = 0.f;
        for (int j = 0; j < 128; j++) {
            float w = Wl2[t * 128 + j];
            wp = fmaf(w, Wd[j], wp);
            wq = fmaf(w, Wd[128 + j], wq);
        }
        g_wP[t] = wp;
        g_wQ[t] = wq;
    }
    if (t >= 128 && t < 224) {
        for (int c = t - 128; c < 128; c += 96) {
            float u = 0.f, v = 0.f;
            for (int k = 0; k < 128; k++) {
                float w = We2[k * 128 + c];
                u = fmaf(W_em[k], w, u);
                v = fmaf(b_em[k], w, v);
            }
            g_u2[c] = u;
            g_v2[c] = v;
        }
    }
}

// ---------------- CSR build: 2 edges per thread ----------------
__global__ void k_convert(const void* __restrict__ ei, int E) {
    int t = blockIdx.x * blockDim.x + threadIdx.x;
    int e = 2 * t;
    if (e >= E) return;
    bool two = (e + 1 < E);
    int evenE = !(E & 1);
    int s0, d0, s1 = 0, d1 = 0;
    if (g_is64) {
        const long long* p = (const long long*)ei;
        longlong2 sv = ((const longlong2*)p)[t];
        s0 = (int)sv.x;
        if (two) s1 = (int)sv.y;
        if (evenE) {
            longlong2 dv = ((const longlong2*)(p + E))[t];
            d0 = (int)dv.x;
            if (two) d1 = (int)dv.y;
        } else {
            d0 = (int)p[E + e];
            if (two) d1 = (int)p[E + e + 1];
        }
    } else {
        const int* p = (const int*)ei;
        int2 sv = ((const int2*)p)[t];
        s0 = sv.x;
        if (two) s1 = sv.y;
        if (evenE) {
            int2 dv = ((const int2*)(p + E))[t];
            d0 = dv.x;
            if (two) d1 = dv.y;
        } else {
            d0 = p[E + e];
            if (two) d1 = p[E + e + 1];
        }
    }
    if (two) {
        ((int4*)g_sd)[t] = make_int4(s0, d0, s1, d1);
        atomicAdd(&g_cursor[d0], 1);
        atomicAdd(&g_cursor[d1], 1);
    } else {
        g_sd[e] = make_int2(s0, d0);
        atomicAdd(&g_cursor[d0], 1);
    }
}

// ---------------- parallel scan ----------------
__global__ void k_bsum(int n) {
    __shared__ int ws[32];
    int tid = threadIdx.x;                       // 1024
    int base = blockIdx.x * SCAN_TILE;
    int sum = 0;
    #pragma unroll
    for (int k = 0; k < 4; k++) {
        int i = base + tid + k * 1024;
        if (i < n) sum += g_cursor[i];
    }
    int lane = tid & 31, w = tid >> 5;
    #pragma unroll
    for (int off = 16; off; off >>= 1) sum += __shfl_xor_sync(0xffffffffu, sum, off);
    if (lane == 0) ws[w] = sum;
    __syncthreads();
    if (w == 0) {
        int v = ws[lane];
        #pragma unroll
        for (int off = 16; off; off >>= 1) v += __shfl_xor_sync(0xffffffffu, v, off);
        if (lane == 0) g_bsum[blockIdx.x] = v;
    }
}

__global__ void k_scan2(int n, int nb) {
    __shared__ int s[SCAN_TILE];
    __shared__ int ws[32];
    __shared__ int s_boff;
    int tid = threadIdx.x;                        // 1024
    int base = blockIdx.x * SCAN_TILE;
    if (tid < 32) {
        int v = (tid < nb && tid < blockIdx.x) ? g_bsum[tid] : 0;
        #pragma unroll
        for (int off = 16; off; off >>= 1) v += __shfl_xor_sync(0xffffffffu, v, off);
        if (tid == 0) s_boff = v;
    }
    #pragma unroll
    for (int k = 0; k < 4; k++) {
        int i = base + tid + k * 1024;
        s[tid + k * 1024] = (i < n) ? g_cursor[i] : 0;
    }
    __syncthreads();
    int a0 = s[4 * tid], a1 = s[4 * tid + 1], a2 = s[4 * tid + 2], a3 = s[4 * tid + 3];
    int tsum = a0 + a1 + a2 + a3;
    int lane = tid & 31, w = tid >> 5;
    int incl = tsum;
    #pragma unroll
    for (int off = 1; off < 32; off <<= 1) {
        int t = __shfl_up_sync(0xffffffffu, incl, off);
        if (lane >= off) incl += t;
    }
    if (lane == 31) ws[w] = incl;
    __syncthreads();
    if (w == 0) {
        int y = ws[lane];
        #pragma unroll
        for (int off = 1; off < 32; off <<= 1) {
            int t = __shfl_up_sync(0xffffffffu, y, off);
            if (lane >= off) y += t;
        }
        ws[lane] = y;
    }
    __syncthreads();
    int run = s_boff + incl - tsum + (w > 0 ? ws[w - 1] : 0);
    int pref[4] = {run, run + a0, run + a0 + a1, run + a0 + a1 + a2};
    int av[4] = {a0, a1, a2, a3};
    #pragma unroll
    for (int k = 0; k < 4; k++) {
        int i = base + 4 * tid + k;
        if (i < n) { g_rowptr[i] = pref[k]; g_cursor[i] = pref[k]; }
        if (i == n - 1) g_rowptr[n] = pref[k] + av[k];
    }
}

// ---------------- scatter: 4 edges per thread ----------------
__global__ void k_scatter(const float* __restrict__ ea, int E) {
    int t = blockIdx.x * blockDim.x + threadIdx.x;
    int e = 4 * t;
    if (e >= E) return;
    if (e + 4 <= E) {
        int4 sdA = ((const int4*)g_sd)[2 * t];
        int4 sdB = ((const int4*)g_sd)[2 * t + 1];
        float4 av = ((const float4*)ea)[t];
        int pos0 = atomicAdd(&g_cursor[sdA.y], 1);
        int pos1 = atomicAdd(&g_cursor[sdA.w], 1);
        int pos2 = atomicAdd(&g_cursor[sdB.y], 1);
        int pos3 = atomicAdd(&g_cursor[sdB.w], 1);
        g_pair[pos0] = make_int2(sdA.x, __float_as_int(av.x));
        g_pair[pos1] = make_int2(sdA.z, __float_as_int(av.y));
        g_pair[pos2] = make_int2(sdB.x, __float_as_int(av.z));
        g_pair[pos3] = make_int2(sdB.z, __float_as_int(av.w));
    } else {
        for (int j = e; j < E; j++) {
            int2 sd = g_sd[j];
            int pos = atomicAdd(&g_cursor[sd.y], 1);
            g_pair[pos] = make_int2(sd.x, __float_as_int(ea[j]));
        }
    }
}

// ---------------- fused layer1 + lin2 + PQ scalars ----------------
// Phase 1 lane layout: lane = eSub*8 + h (4 edge-slots x 8 heads).
// Each lane owns one head's online softmax over its edge subset; full lane
// utilization at any degree; 2-stage eSub butterfly epilogue.
__global__ void k_layer12(const float* __restrict__ x,
                          const float* __restrict__ att1, const float* __restrict__ bias1,
                          const float* __restrict__ Wl, const float* __restrict__ bl,
                          const float* __restrict__ Wr, const float* __restrict__ br,
                          int N)
{
    __shared__ float4 scT[64];   // transposed: scT[c*8+h] = cpack[h*8+c]
    __shared__ float  saT[64];   // saT[c*8+h] = att1[h*8+c]
    __shared__ float  sb1[64];
    __shared__ float  swP[64], swQ[64];
    __shared__ float  sH[64 * 64];       // h1 tile, 16 KB
    int tid = threadIdx.x;               // 256
    if (tid < 64) {
        int hh = tid >> 3, cc = tid & 7;
        scT[cc * 8 + hh] = g_cpack[tid];
        saT[cc * 8 + hh] = att1[tid];
        sb1[tid] = bias1[tid];
        swP[tid] = g_wP[tid]; swQ[tid] = g_wQ[tid];
    }
    __syncthreads();
    int warp = tid >> 5, lane = tid & 31;
    int h = lane & 7;                    // head owned by this lane
    int eSub = lane >> 3;                // edge slot 0..3
    int tile0 = blockIdx.x * 64;

    for (int r = 0; r < 8; r++) {
        int n = tile0 + warp * 8 + r;
        int nl = warp * 8 + r;
        if (n >= N) break;
        int beg = g_rowptr[n], end = g_rowptr[n + 1];
        float xd = x[n];

        float mx = -1e30f, den = 0.f, s1 = 0.f;

        for (int base = beg; base < end; base += 8) {
            int eA = base + eSub, eB = base + 4 + eSub;
            bool vA = eA < end, vB = eB < end;
            int2 pA = vA ? g_pair[eA] : make_int2(0, 0);
            int2 pB = vB ? g_pair[eB] : make_int2(0, 0);
            float xsA = x[pA.x], xsB = x[pB.x];
            float aA = __int_as_float(pA.y), aB = __int_as_float(pB.y);
            float sA = 0.f, sB = 0.f;
            #pragma unroll
            for (int c = 0; c < 8; c++) {
                float4 q = scT[c * 8 + h];
                float w = saT[c * 8 + h];
                float zA = fmaf(q.x, xsA, fmaf(q.y, xd, fmaf(q.z, aA, q.w)));
                float zB = fmaf(q.x, xsB, fmaf(q.y, xd, fmaf(q.z, aB, q.w)));
                zA = zA > 0.f ? zA : 0.2f * zA;
                zB = zB > 0.f ? zB : 0.2f * zB;
                sA = fmaf(zA, w, sA);
                sB = fmaf(zB, w, sB);
            }
            if (!vB) sB = -1e30f;
            if (vA) {
                float mb = fmaxf(sA, sB);
                float e0 = __expf(sA - mb), e1 = __expf(sB - mb);
                float mnew = fmaxf(mx, mb);
                float corr  = __expf(mx - mnew);
                float scale = __expf(mb - mnew);
                den = fmaf(den, corr, (e0 + e1) * scale);
                s1  = fmaf(s1,  corr, fmaf(e0, xsA, e1 * xsB) * scale);
                mx = mnew;
            }
        }
        // merge across the 4 eSub slots of each head (xor 8, 16)
        #pragma unroll
        for (int off = 8; off <= 16; off <<= 1) {
            float mo = __shfl_xor_sync(0xffffffffu, mx,  off);
            float dn = __shfl_xor_sync(0xffffffffu, den, off);
            float so = __shfl_xor_sync(0xffffffffu, s1,  off);
            float M = fmaxf(mx, mo);
            float ca = __expf(mx - M), cb = __expf(mo - M);
            den = fmaf(den, ca, dn * cb);
            s1  = fmaf(s1,  ca, so * cb);
            mx = M;
        }
        // every lane now holds the merged (den, s1) of its head h
        float S1v = s1 / fmaxf(den, 1e-16f);

        float s0 = (end > beg) ? 1.f : 0.f;
        float o0, o1;
        {
            int j = lane;
            float S1 = __shfl_sync(0xffffffffu, S1v, j >> 3);
            o0 = fmaf(g_aggA[j], S1, fmaf(g_aggC[j], s0, sb1[j]));
            o0 = o0 > 0.f ? o0 : expm1f(o0);
            sH[nl * 64 + j] = o0;
        }
        {
            int j = lane + 32;
            float S1 = __shfl_sync(0xffffffffu, S1v, j >> 3);
            o1 = fmaf(g_aggA[j], S1, fmaf(g_aggC[j], s0, sb1[j]));
            o1 = o1 > 0.f ? o1 : expm1f(o1);
            sH[nl * 64 + j] = o1;
        }
        float pv = fmaf(o0, swP[lane], o1 * swP[lane + 32]);
        float qv = fmaf(o0, swQ[lane], o1 * swQ[lane + 32]);
        #pragma unroll
        for (int off = 16; off; off >>= 1) {
            pv += __shfl_xor_sync(0xffffffffu, pv, off);
            qv += __shfl_xor_sync(0xffffffffu, qv, off);
        }
        if (lane == 0) g_pq[n] = make_float2(pv + g_cP, qv + g_cQ);
    }
    __syncthreads();

    // ---- phase 2: two GEMVs from smem h1; xl side stored as fp16 ----
    int half = tid >> 7;                   // 0 -> xl2h (fp16), 1 -> xr2 (fp32)
    int col  = tid & 127;
    const float* W = half ? Wr : Wl;
    const float* b = half ? br : bl;

    float wcol[64];
    float bb = b[col];
    #pragma unroll
    for (int k = 0; k < 64; k++) wcol[k] = W[k * 128 + col];

    int rows = min(64, N - tile0);
    for (int r = 0; r < rows; r++) {
        const float4* rv4 = (const float4*)&sH[r * 64];
        float acc = bb;
        #pragma unroll
        for (int k4 = 0; k4 < 16; k4++) {
            float4 rv = rv4[k4];
            acc = fmaf(rv.x, wcol[4 * k4 + 0], acc);
            acc = fmaf(rv.y, wcol[4 * k4 + 1], acc);
            acc = fmaf(rv.z, wcol[4 * k4 + 2], acc);
            acc = fmaf(rv.w, wcol[4 * k4 + 3], acc);
        }
        size_t idx = (size_t)(tile0 + r) * 128 + col;
        if (half) g_xr2[idx] = acc;
        else      g_xl2h[idx] = __float2half(acc);
    }
}

// ---------------- layer 2 attention: 16-lane edge groups (group-scoped masks) ----------------
__global__ void k_attn2(const float* __restrict__ att2, int N)
{
    __shared__ float su[128], sv[128], sat[128];
    int tid = threadIdx.x;  // 256
    if (tid < 128) { su[tid] = g_u2[tid]; sv[tid] = g_v2[tid]; sat[tid] = att2[tid]; }
    __syncthreads();
    int warp = tid >> 5, lane = tid & 31;
    int grp = lane >> 4, sl = lane & 15;
    unsigned gmask = 0xFFFFu << (grp * 16);    // group-scoped shuffle mask
    int n = blockIdx.x * 8 + warp;
    if (n >= N) return;
    int beg = g_rowptr[n], end = g_rowptr[n + 1];
    int len = end - beg;
    int mid = beg + ((len + 1) >> 1);
    int gbeg = grp ? mid : beg;
    int gend = grp ? end : mid;

    float u[8], vv[8], at[8];
    {
        const float4* xr4 = (const float4*)(&g_xr2[(size_t)n * 128]);
        float4 xa = xr4[sl * 2], xb = xr4[sl * 2 + 1];
        float xrv[8] = {xa.x, xa.y, xa.z, xa.w, xb.x, xb.y, xb.z, xb.w};
        #pragma unroll
        for (int k = 0; k < 8; k++) {
            int ch = sl * 8 + k;
            u[k]  = su[ch];
            vv[k] = sv[ch] + xrv[k];
            at[k] = sat[ch];
        }
    }

    float mx = -1e30f, den = 0.f, accP = 0.f, accQ = 0.f;

    int i = gbeg;
    for (; i + 2 <= gend; i += 2) {
        int2 pr0 = g_pair[i], pr1 = g_pair[i + 1];
        uint4 h0 = ((const uint4*)g_xl2h)[(size_t)pr0.x * 16 + sl];
        uint4 h1 = ((const uint4*)g_xl2h)[(size_t)pr1.x * 16 + sl];
        float2 pq0 = g_pq[pr0.x], pq1 = g_pq[pr1.x];
        float a0 = __int_as_float(pr0.y), a1 = __int_as_float(pr1.y);
        float2 c00 = __half22float2(*(__half2*)&h0.x), c01 = __half22float2(*(__half2*)&h0.y);
        float2 c02 = __half22float2(*(__half2*)&h0.z), c03 = __half22float2(*(__half2*)&h0.w);
        float2 c10 = __half22float2(*(__half2*)&h1.x), c11 = __half22float2(*(__half2*)&h1.y);
        float2 c12 = __half22float2(*(__half2*)&h1.z), c13 = __half22float2(*(__half2*)&h1.w);
        float xl0[8] = {c00.x, c00.y, c01.x, c01.y, c02.x, c02.y, c03.x, c03.y};
        float xl1[8] = {c10.x, c10.y, c11.x, c11.y, c12.x, c12.y, c13.x, c13.y};
        float s0 = 0.f, s1 = 0.f;
        #pragma unroll
        for (int k = 0; k < 8; k++) {
            float m0 = xl0[k] + fmaf(a0, u[k], vv[k]);
            float m1 = xl1[k] + fmaf(a1, u[k], vv[k]);
            m0 = m0 > 0.f ? m0 : 0.2f * m0;
            m1 = m1 > 0.f ? m1 : 0.2f * m1;
            s0 = fmaf(m0, at[k], s0);
            s1 = fmaf(m1, at[k], s1);
        }
        #pragma unroll
        for (int off = 8; off; off >>= 1) {
            s0 += __shfl_xor_sync(gmask, s0, off, 16);
            s1 += __shfl_xor_sync(gmask, s1, off, 16);
        }
        float mb = fmaxf(s0, s1);
        float e0 = __expf(s0 - mb), e1 = __expf(s1 - mb);
        float mnew = fmaxf(mx, mb);
        float corr  = __expf(mx - mnew);
        float scale = __expf(mb - mnew);
        den  = fmaf(den,  corr, (e0 + e1) * scale);
        accP = fmaf(accP, corr, fmaf(e0, pq0.x, e1 * pq1.x) * scale);
        accQ = fmaf(accQ, corr, fmaf(e0, pq0.y, e1 * pq1.y) * scale);
        mx = mnew;
    }
    if (i < gend) {
        int2 pr = g_pair[i];
        uint4 h0 = ((const uint4*)g_xl2h)[(size_t)pr.x * 16 + sl];
        float2 pqv = g_pq[pr.x];
        float a = __int_as_float(pr.y);
        float2 c0 = __half22float2(*(__half2*)&h0.x), c1 = __half22float2(*(__half2*)&h0.y);
        float2 c2 = __half22float2(*(__half2*)&h0.z), c3 = __half22float2(*(__half2*)&h0.w);
        float xl[8] = {c0.x, c0.y, c1.x, c1.y, c2.x, c2.y, c3.x, c3.y};
        float s0 = 0.f;
        #pragma unroll
        for (int k = 0; k < 8; k++) {
            float m = xl[k] + fmaf(a, u[k], vv[k]);
            m = m > 0.f ? m : 0.2f * m;
            s0 = fmaf(m, at[k], s0);
        }
        #pragma unroll
        for (int off = 8; off; off >>= 1)
            s0 += __shfl_xor_sync(gmask, s0, off, 16);
        float mnew = fmaxf(mx, s0);
        float corr = __expf(mx - mnew);
        float ex   = __expf(s0 - mnew);
        den  = fmaf(den,  corr, ex);
        accP = fmaf(accP, corr, ex * pqv.x);
        accQ = fmaf(accQ, corr, ex * pqv.y);
        mx = mnew;
    }
    __syncwarp();
    float Mo = __shfl_xor_sync(0xffffffffu, mx, 16);
    float M  = fmaxf(mx, Mo);
    float corr = __expf(mx - M);
    float d  = den  * corr;
    float pp = accP * corr;
    float qq = accQ * corr;
    d  += __shfl_xor_sync(0xffffffffu, d, 16);
    pp += __shfl_xor_sync(0xffffffffu, pp, 16);
    qq += __shfl_xor_sync(0xffffffffu, qq, 16);
    d = fmaxf(d, 1e-16f);
    if (lane == 0) {
        g_p[n] = pp / d + g_cB1;
        g_q[n] = qq / d + g_cB2;
    }
}

// ---------------- final edge output: 2 edges per thread ----------------
__global__ void k_final(const float* __restrict__ bd, float* __restrict__ out, int E) {
    int t = blockIdx.x * blockDim.x + threadIdx.x;
    int e = 2 * t;
    if (e >= E) return;
    float b = bd[0];
    if (e + 1 < E) {
        int4 sd2 = ((const int4*)g_sd)[t];
        float2 o;
        o.x = g_p[sd2.x] + g_q[sd2.y] + b;
        o.y = g_p[sd2.z] + g_q[sd2.w] + b;
        ((float2*)out)[t] = o;
    } else {
        int2 sd = g_sd[e];
        out[e] = g_p[sd.x] + g_q[sd.y] + b;
    }
}

// ---------------- launch ----------------
extern "C" void kernel_launch(void* const* d_in, const int* in_sizes, int n_in,
                              void* d_out, int out_size)
{
    const float* x     = (const float*)d_in[0];
    const void*  ei    = d_in[1];
    const float* ea    = (const float*)d_in[2];
    const float* W_em  = (const float*)d_in[3];
    const float* b_em  = (const float*)d_in[4];
    const float* W0    = (const float*)d_in[5];
    const float* b0    = (const float*)d_in[6];
    const float* Wl1   = (const float*)d_in[7];
    const float* bl1   = (const float*)d_in[8];
    const float* Wr1   = (const float*)d_in[9];
    const float* br1   = (const float*)d_in[10];
    const float* We1   = (const float*)d_in[11];
    const float* att1  = (const float*)d_in[12];
    const float* bias1 = (const float*)d_in[13];
    const float* Wl2   = (const float*)d_in[14];
    const float* bl2   = (const float*)d_in[15];
    const float* Wr2   = (const float*)d_in[16];
    const float* br2   = (const float*)d_in[17];
    const float* We2   = (const float*)d_in[18];
    const float* att2  = (const float*)d_in[19];
    const float* bias2 = (const float*)d_in[20];
    const float* Wd    = (const float*)d_in[21];
    const float* bd    = (const float*)d_in[22];
    float* out = (float*)d_out;

    int N = in_sizes[0];
    int E = in_sizes[2];
    int NB = (N + SCAN_TILE - 1) / SCAN_TILE;
    int Eh = (E + 1) / 2;
    int Eq = (E + 3) / 4;

    k_prez<<<(N + 255) / 256, 256>>>(W_em, b_em, W0, b0, Wl1, bl1, Wr1, br1, We1, We2,
                                     Wl2, bl2, bias2, Wd, ei, N);
    k_convert<<<(Eh + 255) / 256, 256>>>(ei, E);
    k_bsum<<<NB, 1024>>>(N);
    k_scan2<<<NB, 1024>>>(N, NB);
    k_scatter<<<(Eq + 255) / 256, 256>>>(ea, E);
    k_layer12<<<(N + 63) / 64, 256>>>(x, att1, bias1, Wl2, bl2, Wr2, br2, N);
    k_attn2<<<(N + 7) / 8, 256>>>(att2, N);
    k_final<<<(Eh + 255) / 256, 256>>>(bd, out, E);
}

// round 17
// speedup vs baseline: 1.4956x; 1.0393x over previous
#include <cuda_runtime.h>
#include <cuda_bf16.h>
#include <cuda_fp16.h>
#include <math.h>

#define MAXN 50000
#define MAXE 800000
#define SCAN_TILE 4096
#define MAX_BLKS ((MAXN + SCAN_TILE - 1) / SCAN_TILE + 1)

// ---------------- scratch (device globals; no allocation allowed) ----------------
__device__ int   g_is64;
__device__ __align__(16) int2  g_sd[MAXE];   // (src, dst) original order
__device__ int   g_rowptr[MAXN + 1];
__device__ int   g_cursor[MAXN];
__device__ int2  g_pair[MAXE];               // (src, ea-bits) sorted by dst
__device__ int   g_bsum[MAX_BLKS];
__device__ __align__(16) __half g_xl2h[(size_t)MAXN * 128];  // fp16 score operand
__device__ __align__(16) float  g_xr2[(size_t)MAXN * 128];
__device__ __align__(16) float2 g_pq[MAXN];  // (P, Q) per-node projection scalars
__device__ float g_p[MAXN];
__device__ float g_q[MAXN];
__device__ __align__(16) float4 g_cpack[64]; // (cS, cD, cE, cC) per channel
__device__ float g_aggA[64];
__device__ float g_aggC[64];
__device__ float g_u2[128];
__device__ float g_v2[128];
__device__ float g_wP[64];     // Wl2 @ Wd[:128]
__device__ float g_wQ[64];     // Wl2 @ Wd[128:]
__device__ float g_cP, g_cQ;   // bl2 @ Wd halves
__device__ float g_cB1, g_cB2; // bias2 @ Wd halves

// ---------------- precompute + int64 detect + cursor zero (fused) ----------------
__global__ void k_prez(const float* __restrict__ W_em, const float* __restrict__ b_em,
                       const float* __restrict__ W0,   const float* __restrict__ b0,
                       const float* __restrict__ Wl1,  const float* __restrict__ bl1,
                       const float* __restrict__ Wr1,  const float* __restrict__ br1,
                       const float* __restrict__ We1,  const float* __restrict__ We2,
                       const float* __restrict__ Wl2,  const float* __restrict__ bl2,
                       const float* __restrict__ bias2,const float* __restrict__ Wd,
                       const void* __restrict__ ei, int N)
{
    int i = blockIdx.x * blockDim.x + threadIdx.x;
    if (i < N) g_cursor[i] = 0;
    if (blockIdx.x != 0) return;
    int t = threadIdx.x;
    if (t == 0) {
        const long long* p = (const long long*)ei;
        int is64 = 1;
        for (int k = 0; k < 8; k++) {
            long long v = p[k];
            if (v < 0 || v >= (1LL << 31)) { is64 = 0; break; }
        }
        g_is64 = is64;
    }
    if (t >= 224 && t < 256) {
        int lane = t - 224;
        float cP = 0.f, cQ = 0.f, c1 = 0.f, c2 = 0.f;
        for (int j = lane; j < 128; j += 32) {
            float w1 = Wd[j], w2 = Wd[128 + j];
            cP = fmaf(bl2[j],   w1, cP);
            cQ = fmaf(bl2[j],   w2, cQ);
            c1 = fmaf(bias2[j], w1, c1);
            c2 = fmaf(bias2[j], w2, c2);
        }
        #pragma unroll
        for (int off = 16; off; off >>= 1) {
            cP += __shfl_xor_sync(0xffffffffu, cP, off);
            cQ += __shfl_xor_sync(0xffffffffu, cQ, off);
            c1 += __shfl_xor_sync(0xffffffffu, c1, off);
            c2 += __shfl_xor_sync(0xffffffffu, c2, off);
        }
        if (lane == 0) { g_cP = cP; g_cQ = cQ; g_cB1 = c1; g_cB2 = c2; }
    }
    if (t < 64) {
        float cS = 0.f, cD = 0.f, cE = 0.f;
        float Cl = bl1[t], Cr = br1[t], v1 = 0.f;
        for (int k = 0; k < 128; k++) {
            float wl = Wl1[k * 64 + t];
            float wr = Wr1[k * 64 + t];
            float we = We1[k * 64 + t];
            cS += W0[k]   * wl;
            cD += W0[k]   * wr;
            cE += W_em[k] * we;
            Cl += b0[k]   * wl;
            Cr += b0[k]   * wr;
            v1 += b_em[k] * we;
        }
        g_cpack[t] = make_float4(cS, cD, cE, Cl + Cr + v1);
        g_aggA[t] = cS;
        g_aggC[t] = Cl;
        float wp = 0.f, wq = 0.f;
        for (int j = 0; j < 128; j++) {
            float w = Wl2[t * 128 + j];
            wp = fmaf(w, Wd[j], wp);
            wq = fmaf(w, Wd[128 + j], wq);
        }
        g_wP[t] = wp;
        g_wQ[t] = wq;
    }
    if (t >= 128 && t < 224) {
        for (int c = t - 128; c < 128; c += 96) {
            float u = 0.f, v = 0.f;
            for (int k = 0; k < 128; k++) {
                float w = We2[k * 128 + c];
                u = fmaf(W_em[k], w, u);
                v = fmaf(b_em[k], w, v);
            }
            g_u2[c] = u;
            g_v2[c] = v;
        }
    }
}

// ---------------- CSR build: 2 edges per thread ----------------
__global__ void k_convert(const void* __restrict__ ei, int E) {
    int t = blockIdx.x * blockDim.x + threadIdx.x;
    int e = 2 * t;
    if (e >= E) return;
    bool two = (e + 1 < E);
    int evenE = !(E & 1);
    int s0, d0, s1 = 0, d1 = 0;
    if (g_is64) {
        const long long* p = (const long long*)ei;
        longlong2 sv = ((const longlong2*)p)[t];
        s0 = (int)sv.x;
        if (two) s1 = (int)sv.y;
        if (evenE) {
            longlong2 dv = ((const longlong2*)(p + E))[t];
            d0 = (int)dv.x;
            if (two) d1 = (int)dv.y;
        } else {
            d0 = (int)p[E + e];
            if (two) d1 = (int)p[E + e + 1];
        }
    } else {
        const int* p = (const int*)ei;
        int2 sv = ((const int2*)p)[t];
        s0 = sv.x;
        if (two) s1 = sv.y;
        if (evenE) {
            int2 dv = ((const int2*)(p + E))[t];
            d0 = dv.x;
            if (two) d1 = dv.y;
        } else {
            d0 = p[E + e];
            if (two) d1 = p[E + e + 1];
        }
    }
    if (two) {
        ((int4*)g_sd)[t] = make_int4(s0, d0, s1, d1);
        atomicAdd(&g_cursor[d0], 1);
        atomicAdd(&g_cursor[d1], 1);
    } else {
        g_sd[e] = make_int2(s0, d0);
        atomicAdd(&g_cursor[d0], 1);
    }
}

// ---------------- parallel scan ----------------
__global__ void k_bsum(int n) {
    __shared__ int ws[32];
    int tid = threadIdx.x;                       // 1024
    int base = blockIdx.x * SCAN_TILE;
    int sum = 0;
    #pragma unroll
    for (int k = 0; k < 4; k++) {
        int i = base + tid + k * 1024;
        if (i < n) sum += g_cursor[i];
    }
    int lane = tid & 31, w = tid >> 5;
    #pragma unroll
    for (int off = 16; off; off >>= 1) sum += __shfl_xor_sync(0xffffffffu, sum, off);
    if (lane == 0) ws[w] = sum;
    __syncthreads();
    if (w == 0) {
        int v = ws[lane];
        #pragma unroll
        for (int off = 16; off; off >>= 1) v += __shfl_xor_sync(0xffffffffu, v, off);
        if (lane == 0) g_bsum[blockIdx.x] = v;
    }
}

__global__ void k_scan2(int n, int nb) {
    __shared__ int s[SCAN_TILE];
    __shared__ int ws[32];
    __shared__ int s_boff;
    int tid = threadIdx.x;                        // 1024
    int base = blockIdx.x * SCAN_TILE;
    if (tid < 32) {
        int v = (tid < nb && tid < blockIdx.x) ? g_bsum[tid] : 0;
        #pragma unroll
        for (int off = 16; off; off >>= 1) v += __shfl_xor_sync(0xffffffffu, v, off);
        if (tid == 0) s_boff = v;
    }
    #pragma unroll
    for (int k = 0; k < 4; k++) {
        int i = base + tid + k * 1024;
        s[tid + k * 1024] = (i < n) ? g_cursor[i] : 0;
    }
    __syncthreads();
    int a0 = s[4 * tid], a1 = s[4 * tid + 1], a2 = s[4 * tid + 2], a3 = s[4 * tid + 3];
    int tsum = a0 + a1 + a2 + a3;
    int lane = tid & 31, w = tid >> 5;
    int incl = tsum;
    #pragma unroll
    for (int off = 1; off < 32; off <<= 1) {
        int t = __shfl_up_sync(0xffffffffu, incl, off);
        if (lane >= off) incl += t;
    }
    if (lane == 31) ws[w] = incl;
    __syncthreads();
    if (w == 0) {
        int y = ws[lane];
        #pragma unroll
        for (int off = 1; off < 32; off <<= 1) {
            int t = __shfl_up_sync(0xffffffffu, y, off);
            if (lane >= off) y += t;
        }
        ws[lane] = y;
    }
    __syncthreads();
    int run = s_boff + incl - tsum + (w > 0 ? ws[w - 1] : 0);
    int pref[4] = {run, run + a0, run + a0 + a1, run + a0 + a1 + a2};
    int av[4] = {a0, a1, a2, a3};
    #pragma unroll
    for (int k = 0; k < 4; k++) {
        int i = base + 4 * tid + k;
        if (i < n) { g_rowptr[i] = pref[k]; g_cursor[i] = pref[k]; }
        if (i == n - 1) g_rowptr[n] = pref[k] + av[k];
    }
}

// ---------------- scatter: 4 edges per thread ----------------
__global__ void k_scatter(const float* __restrict__ ea, int E) {
    int t = blockIdx.x * blockDim.x + threadIdx.x;
    int e = 4 * t;
    if (e >= E) return;
    if (e + 4 <= E) {
        int4 sdA = ((const int4*)g_sd)[2 * t];
        int4 sdB = ((const int4*)g_sd)[2 * t + 1];
        float4 av = ((const float4*)ea)[t];
        int pos0 = atomicAdd(&g_cursor[sdA.y], 1);
        int pos1 = atomicAdd(&g_cursor[sdA.w], 1);
        int pos2 = atomicAdd(&g_cursor[sdB.y], 1);
        int pos3 = atomicAdd(&g_cursor[sdB.w], 1);
        g_pair[pos0] = make_int2(sdA.x, __float_as_int(av.x));
        g_pair[pos1] = make_int2(sdA.z, __float_as_int(av.y));
        g_pair[pos2] = make_int2(sdB.x, __float_as_int(av.z));
        g_pair[pos3] = make_int2(sdB.z, __float_as_int(av.w));
    } else {
        for (int j = e; j < E; j++) {
            int2 sd = g_sd[j];
            int pos = atomicAdd(&g_cursor[sd.y], 1);
            g_pair[pos] = make_int2(sd.x, __float_as_int(ea[j]));
        }
    }
}

// ---------------- fused layer1 + lin2 + PQ scalars (head-per-lane, no-max softmax) ----------------
__global__ void k_layer12(const float* __restrict__ x,
                          const float* __restrict__ att1, const float* __restrict__ bias1,
                          const float* __restrict__ Wl, const float* __restrict__ bl,
                          const float* __restrict__ Wr, const float* __restrict__ br,
                          int N)
{
    __shared__ float4 scT[64];   // transposed: scT[c*8+h] = cpack[h*8+c]
    __shared__ float  saT[64];   // saT[c*8+h] = att1[h*8+c]
    __shared__ float  sb1[64];
    __shared__ float  swP[64], swQ[64];
    __shared__ float  sH[64 * 64];       // h1 tile, 16 KB
    int tid = threadIdx.x;               // 256
    if (tid < 64) {
        int hh = tid >> 3, cc = tid & 7;
        scT[cc * 8 + hh] = g_cpack[tid];
        saT[cc * 8 + hh] = att1[tid];
        sb1[tid] = bias1[tid];
        swP[tid] = g_wP[tid]; swQ[tid] = g_wQ[tid];
    }
    __syncthreads();
    int warp = tid >> 5, lane = tid & 31;
    int h = lane & 7;                    // head owned by this lane
    int eSub = lane >> 3;                // edge slot 0..3
    int tile0 = blockIdx.x * 64;

    for (int r = 0; r < 8; r++) {
        int n = tile0 + warp * 8 + r;
        int nl = warp * 8 + r;
        if (n >= N) break;
        int beg = g_rowptr[n], end = g_rowptr[n + 1];
        float xd = x[n];

        float den = 0.f, s1 = 0.f;

        for (int base = beg; base < end; base += 8) {
            int eA = base + eSub, eB = base + 4 + eSub;
            bool vA = eA < end, vB = eB < end;
            int2 pA = vA ? g_pair[eA] : make_int2(0, 0);
            int2 pB = vB ? g_pair[eB] : make_int2(0, 0);
            float xsA = x[pA.x], xsB = x[pB.x];
            float aA = __int_as_float(pA.y), aB = __int_as_float(pB.y);
            float sA = 0.f, sB = 0.f;
            #pragma unroll
            for (int c = 0; c < 8; c++) {
                float4 q = scT[c * 8 + h];
                float w = saT[c * 8 + h];
                float zA = fmaf(q.x, xsA, fmaf(q.y, xd, fmaf(q.z, aA, q.w)));
                float zB = fmaf(q.x, xsB, fmaf(q.y, xd, fmaf(q.z, aB, q.w)));
                zA = zA > 0.f ? zA : 0.2f * zA;
                zB = zB > 0.f ? zB : 0.2f * zB;
                sA = fmaf(zA, w, sA);
                sB = fmaf(zB, w, sB);
            }
            if (!vA) sA = -1e30f;            // exp -> exactly 0
            if (!vB) sB = -1e30f;
            float e0 = __expf(sA), e1 = __expf(sB);
            den += e0 + e1;
            s1 = fmaf(e0, xsA, fmaf(e1, xsB, s1));
        }
        // merge across the 4 eSub slots of each head (plain adds)
        #pragma unroll
        for (int off = 8; off <= 16; off <<= 1) {
            den += __shfl_xor_sync(0xffffffffu, den, off);
            s1  += __shfl_xor_sync(0xffffffffu, s1,  off);
        }
        float S1v = s1 / fmaxf(den, 1e-16f);

        float s0 = (end > beg) ? 1.f : 0.f;
        float o0, o1;
        {
            int j = lane;
            float S1 = __shfl_sync(0xffffffffu, S1v, j >> 3);
            o0 = fmaf(g_aggA[j], S1, fmaf(g_aggC[j], s0, sb1[j]));
            o0 = o0 > 0.f ? o0 : expm1f(o0);
            sH[nl * 64 + j] = o0;
        }
        {
            int j = lane + 32;
            float S1 = __shfl_sync(0xffffffffu, S1v, j >> 3);
            o1 = fmaf(g_aggA[j], S1, fmaf(g_aggC[j], s0, sb1[j]));
            o1 = o1 > 0.f ? o1 : expm1f(o1);
            sH[nl * 64 + j] = o1;
        }
        float pv = fmaf(o0, swP[lane], o1 * swP[lane + 32]);
        float qv = fmaf(o0, swQ[lane], o1 * swQ[lane + 32]);
        #pragma unroll
        for (int off = 16; off; off >>= 1) {
            pv += __shfl_xor_sync(0xffffffffu, pv, off);
            qv += __shfl_xor_sync(0xffffffffu, qv, off);
        }
        if (lane == 0) g_pq[n] = make_float2(pv + g_cP, qv + g_cQ);
    }
    __syncthreads();

    // ---- phase 2: two GEMVs from smem h1; xl side stored as fp16 ----
    int half = tid >> 7;                   // 0 -> xl2h (fp16), 1 -> xr2 (fp32)
    int col  = tid & 127;
    const float* W = half ? Wr : Wl;
    const float* b = half ? br : bl;

    float wcol[64];
    float bb = b[col];
    #pragma unroll
    for (int k = 0; k < 64; k++) wcol[k] = W[k * 128 + col];

    int rows = min(64, N - tile0);
    for (int r = 0; r < rows; r++) {
        const float4* rv4 = (const float4*)&sH[r * 64];
        float acc = bb;
        #pragma unroll
        for (int k4 = 0; k4 < 16; k4++) {
            float4 rv = rv4[k4];
            acc = fmaf(rv.x, wcol[4 * k4 + 0], acc);
            acc = fmaf(rv.y, wcol[4 * k4 + 1], acc);
            acc = fmaf(rv.z, wcol[4 * k4 + 2], acc);
            acc = fmaf(rv.w, wcol[4 * k4 + 3], acc);
        }
        size_t idx = (size_t)(tile0 + r) * 128 + col;
        if (half) g_xr2[idx] = acc;
        else      g_xl2h[idx] = __float2half(acc);
    }
}

// ---------------- layer 2 attention: 16-lane groups, no-max softmax ----------------
__global__ void k_attn2(const float* __restrict__ att2, int N)
{
    __shared__ float su[128], sv[128], sat[128];
    int tid = threadIdx.x;  // 256
    if (tid < 128) { su[tid] = g_u2[tid]; sv[tid] = g_v2[tid]; sat[tid] = att2[tid]; }
    __syncthreads();
    int warp = tid >> 5, lane = tid & 31;
    int grp = lane >> 4, sl = lane & 15;
    unsigned gmask = 0xFFFFu << (grp * 16);    // group-scoped shuffle mask
    int n = blockIdx.x * 8 + warp;
    if (n >= N) return;
    int beg = g_rowptr[n], end = g_rowptr[n + 1];
    int len = end - beg;
    int mid = beg + ((len + 1) >> 1);
    int gbeg = grp ? mid : beg;
    int gend = grp ? end : mid;

    float u[8], vv[8], at[8];
    {
        const float4* xr4 = (const float4*)(&g_xr2[(size_t)n * 128]);
        float4 xa = xr4[sl * 2], xb = xr4[sl * 2 + 1];
        float xrv[8] = {xa.x, xa.y, xa.z, xa.w, xb.x, xb.y, xb.z, xb.w};
        #pragma unroll
        for (int k = 0; k < 8; k++) {
            int ch = sl * 8 + k;
            u[k]  = su[ch];
            vv[k] = sv[ch] + xrv[k];
            at[k] = sat[ch];
        }
    }

    float den = 0.f, accP = 0.f, accQ = 0.f;

    int i = gbeg;
    for (; i + 2 <= gend; i += 2) {
        int2 pr0 = g_pair[i], pr1 = g_pair[i + 1];
        uint4 h0 = ((const uint4*)g_xl2h)[(size_t)pr0.x * 16 + sl];
        uint4 h1 = ((const uint4*)g_xl2h)[(size_t)pr1.x * 16 + sl];
        float2 pq0 = g_pq[pr0.x], pq1 = g_pq[pr1.x];
        float a0 = __int_as_float(pr0.y), a1 = __int_as_float(pr1.y);
        float2 c00 = __half22float2(*(__half2*)&h0.x), c01 = __half22float2(*(__half2*)&h0.y);
        float2 c02 = __half22float2(*(__half2*)&h0.z), c03 = __half22float2(*(__half2*)&h0.w);
        float2 c10 = __half22float2(*(__half2*)&h1.x), c11 = __half22float2(*(__half2*)&h1.y);
        float2 c12 = __half22float2(*(__half2*)&h1.z), c13 = __half22float2(*(__half2*)&h1.w);
        float xl0[8] = {c00.x, c00.y, c01.x, c01.y, c02.x, c02.y, c03.x, c03.y};
        float xl1[8] = {c10.x, c10.y, c11.x, c11.y, c12.x, c12.y, c13.x, c13.y};
        float s0 = 0.f, s1 = 0.f;
        #pragma unroll
        for (int k = 0; k < 8; k++) {
            float m0 = xl0[k] + fmaf(a0, u[k], vv[k]);
            float m1 = xl1[k] + fmaf(a1, u[k], vv[k]);
            m0 = m0 > 0.f ? m0 : 0.2f * m0;
            m1 = m1 > 0.f ? m1 : 0.2f * m1;
            s0 = fmaf(m0, at[k], s0);
            s1 = fmaf(m1, at[k], s1);
        }
        #pragma unroll
        for (int off = 8; off; off >>= 1) {
            s0 += __shfl_xor_sync(gmask, s0, off, 16);
            s1 += __shfl_xor_sync(gmask, s1, off, 16);
        }
        float e0 = __expf(s0), e1 = __expf(s1);
        den += e0 + e1;
        accP = fmaf(e0, pq0.x, fmaf(e1, pq1.x, accP));
        accQ = fmaf(e0, pq0.y, fmaf(e1, pq1.y, accQ));
    }
    if (i < gend) {
        int2 pr = g_pair[i];
        uint4 h0 = ((const uint4*)g_xl2h)[(size_t)pr.x * 16 + sl];
        float2 pqv = g_pq[pr.x];
        float a = __int_as_float(pr.y);
        float2 c0 = __half22float2(*(__half2*)&h0.x), c1 = __half22float2(*(__half2*)&h0.y);
        float2 c2 = __half22float2(*(__half2*)&h0.z), c3 = __half22float2(*(__half2*)&h0.w);
        float xl[8] = {c0.x, c0.y, c1.x, c1.y, c2.x, c2.y, c3.x, c3.y};
        float s0 = 0.f;
        #pragma unroll
        for (int k = 0; k < 8; k++) {
            float m = xl[k] + fmaf(a, u[k], vv[k]);
            m = m > 0.f ? m : 0.2f * m;
            s0 = fmaf(m, at[k], s0);
        }
        #pragma unroll
        for (int off = 8; off; off >>= 1)
            s0 += __shfl_xor_sync(gmask, s0, off, 16);
        float ex = __expf(s0);
        den  += ex;
        accP = fmaf(ex, pqv.x, accP);
        accQ = fmaf(ex, pqv.y, accQ);
    }
    // merge the two 16-lane groups (plain adds at reconvergence)
    __syncwarp();
    den  += __shfl_xor_sync(0xffffffffu, den,  16);
    accP += __shfl_xor_sync(0xffffffffu, accP, 16);
    accQ += __shfl_xor_sync(0xffffffffu, accQ, 16);
    den = fmaxf(den, 1e-16f);
    if (lane == 0) {
        g_p[n] = accP / den + g_cB1;
        g_q[n] = accQ / den + g_cB2;
    }
}

// ---------------- final edge output: 4 edges per thread ----------------
__global__ void k_final(const float* __restrict__ bd, float* __restrict__ out, int E) {
    int t = blockIdx.x * blockDim.x + threadIdx.x;
    int e = 4 * t;
    if (e >= E) return;
    float b = bd[0];
    if (e + 4 <= E) {
        int4 sdA = ((const int4*)g_sd)[2 * t];
        int4 sdB = ((const int4*)g_sd)[2 * t + 1];
        float4 o;
        o.x = g_p[sdA.x] + g_q[sdA.y] + b;
        o.y = g_p[sdA.z] + g_q[sdA.w] + b;
        o.z = g_p[sdB.x] + g_q[sdB.y] + b;
        o.w = g_p[sdB.z] + g_q[sdB.w] + b;
        ((float4*)out)[t] = o;
    } else {
        for (int j = e; j < E; j++) {
            int2 sd = g_sd[j];
            out[j] = g_p[sd.x] + g_q[sd.y] + b;
        }
    }
}

// ---------------- launch ----------------
extern "C" void kernel_launch(void* const* d_in, const int* in_sizes, int n_in,
                              void* d_out, int out_size)
{
    const float* x     = (const float*)d_in[0];
    const void*  ei    = d_in[1];
    const float* ea    = (const float*)d_in[2];
    const float* W_em  = (const float*)d_in[3];
    const float* b_em  = (const float*)d_in[4];
    const float* W0    = (const float*)d_in[5];
    const float* b0    = (const float*)d_in[6];
    const float* Wl1   = (const float*)d_in[7];
    const float* bl1   = (const float*)d_in[8];
    const float* Wr1   = (const float*)d_in[9];
    const float* br1   = (const float*)d_in[10];
    const float* We1   = (const float*)d_in[11];
    const float* att1  = (const float*)d_in[12];
    const float* bias1 = (const float*)d_in[13];
    const float* Wl2   = (const float*)d_in[14];
    const float* bl2   = (const float*)d_in[15];
    const float* Wr2   = (const float*)d_in[16];
    const float* br2   = (const float*)d_in[17];
    const float* We2   = (const float*)d_in[18];
    const float* att2  = (const float*)d_in[19];
    const float* bias2 = (const float*)d_in[20];
    const float* Wd    = (const float*)d_in[21];
    const float* bd    = (const float*)d_in[22];
    float* out = (float*)d_out;

    int N = in_sizes[0];
    int E = in_sizes[2];
    int NB = (N + SCAN_TILE - 1) / SCAN_TILE;
    int Eh = (E + 1) / 2;
    int Eq = (E + 3) / 4;

    k_prez<<<(N + 255) / 256, 256>>>(W_em, b_em, W0, b0, Wl1, bl1, Wr1, br1, We1, We2,
                                     Wl2, bl2, bias2, Wd, ei, N);
    k_convert<<<(Eh + 255) / 256, 256>>>(ei, E);
    k_bsum<<<NB, 1024>>>(N);
    k_scan2<<<NB, 1024>>>(N, NB);
    k_scatter<<<(Eq + 255) / 256, 256>>>(ea, E);
    k_layer12<<<(N + 63) / 64, 256>>>(x, att1, bias1, Wl2, bl2, Wr2, br2, N);
    k_attn2<<<(N + 7) / 8, 256>>>(att2, N);
    k_final<<<(Eq + 255) / 256, 256>>>(bd, out, E);
}